// round 13
// baseline (speedup 1.0000x reference)
#include <cuda_runtime.h>
#include <cuda_bf16.h>
#include <cstdint>
#include <math.h>

#define NB 2048
#define R 116
#define RR 13456
#define NPAIR 6728
#define NF 348
#define H 128
#define H3 384
#define CC 2560
#define C1 1024
#define EPSBN 1e-5f
#define SPLITS 6
#define KCHUNK2 1136
#define CHT 1024
#define SLABS 8

// big tc kernels: stage K=32 (16 u32), row stride 20 u32
#define BS32 20
#define BPL (128*BS32)
#define BIG_SMEM (2*4*BPL*4)
// fused chain kernel: K=128 padded, row stride 68 u32
#define CS32 68
#define CPL (128*CS32)
#define CH_SMEM (6*CPL*4)

// ---------------- scratch ----------------
static __device__ float g_X [(size_t)NB*NF];
static __device__ float g_Z [(size_t)NB*RR];
static __device__ float g_Z2[(size_t)NB*RR];
static __device__ float g_X1[(size_t)NB*NF];
static __device__ float g_Yx[(size_t)NB*H];
static __device__ float g_Yz[(size_t)NB*H3];
static __device__ float g_YzS[(size_t)SPLITS*NB*H3];
static __device__ float g_XZ[(size_t)NB*CC];
static __device__ float g_Hb[(size_t)NB*C1];
static __device__ uint32_t g_Zh[(size_t)NB*NPAIR];
static __device__ uint32_t g_Zl[(size_t)NB*NPAIR];
static __device__ uint32_t g_LWh[(size_t)5*H3*NPAIR];
static __device__ uint32_t g_LWl[(size_t)5*H3*NPAIR];
static __device__ uint32_t g_W2h[NPAIR], g_W2l[NPAIR];
static __device__ uint32_t g_EwTh[NPAIR], g_EwTl[NPAIR];
static __device__ double g_ps[R*SLABS*2];
static __device__ float g_m1[H3], g_r1[H3];
static __device__ float g_mz[R], g_rz[R], g_mx[R], g_rx[R];

// ---------------- helpers ----------------
__device__ __forceinline__ void mma16816(float* c, const uint32_t* a, const uint32_t* b) {
    asm volatile(
        "mma.sync.aligned.m16n8k16.row.col.f32.bf16.bf16.f32 "
        "{%0,%1,%2,%3}, {%4,%5,%6,%7}, {%8,%9}, {%0,%1,%2,%3};\n"
        : "+f"(c[0]), "+f"(c[1]), "+f"(c[2]), "+f"(c[3])
        : "r"(a[0]), "r"(a[1]), "r"(a[2]), "r"(a[3]), "r"(b[0]), "r"(b[1]));
}

__device__ __forceinline__ void ldsm4(uint32_t& r0, uint32_t& r1, uint32_t& r2, uint32_t& r3, uint32_t a) {
    asm volatile("ldmatrix.sync.aligned.m8n8.x4.shared.b16 {%0,%1,%2,%3}, [%4];"
        : "=r"(r0), "=r"(r1), "=r"(r2), "=r"(r3) : "r"(a));
}

__device__ __forceinline__ uint32_t smem_u32(const void* p) {
    uint32_t a;
    asm("{ .reg .u64 t; cvta.to.shared.u64 t, %1; cvt.u32.u64 %0, t; }" : "=r"(a) : "l"(p));
    return a;
}

__device__ __forceinline__ void split2(float x0, float x1, uint32_t& hi, uint32_t& lo) {
    __nv_bfloat16 h0 = __float2bfloat16(x0), h1 = __float2bfloat16(x1);
    float r0 = x0 - __bfloat162float(h0), r1 = x1 - __bfloat162float(h1);
    __nv_bfloat16 l0 = __float2bfloat16(r0), l1 = __float2bfloat16(r1);
    hi = (uint32_t)__bfloat16_as_ushort(h0) | ((uint32_t)__bfloat16_as_ushort(h1) << 16);
    lo = (uint32_t)__bfloat16_as_ushort(l0) | ((uint32_t)__bfloat16_as_ushort(l1) << 16);
}

// ---------------- split kernels ----------------
__global__ void k_split(const float* __restrict__ src, uint32_t* __restrict__ dh,
                        uint32_t* __restrict__ dl, size_t npairs) {
    size_t i = (size_t)blockIdx.x * blockDim.x + threadIdx.x;
    if (i < npairs) {
        float2 v = ((const float2*)src)[i];
        uint32_t h, l; split2(v.x, v.y, h, l);
        dh[i] = h; dl[i] = l;
    }
}

__global__ void k_splitZ0(const float* __restrict__ src, float* __restrict__ dst,
                          uint32_t* __restrict__ dh, uint32_t* __restrict__ dl) {
    size_t i = (size_t)blockIdx.x * blockDim.x + threadIdx.x;
    if (i < (size_t)NB*NPAIR) {
        float2 v = ((const float2*)src)[i];
        ((float2*)dst)[i] = v;
        uint32_t h, l; split2(v.x, v.y, h, l);
        dh[i] = h; dl[i] = l;
    }
}

__global__ void k_prep(const float* __restrict__ w2, const float* __restrict__ ew,
                       uint32_t* __restrict__ w2h, uint32_t* __restrict__ w2l,
                       uint32_t* __restrict__ ewth, uint32_t* __restrict__ ewtl) {
    int i = blockIdx.x * blockDim.x + threadIdx.x;
    if (i < NPAIR) {
        float2 v = ((const float2*)w2)[i];
        uint32_t h, l; split2(v.x, v.y, h, l);
        w2h[i] = h; w2l[i] = l;
        int lrow = i / 58, k2 = i - lrow*58;
        float a0 = ew[(2*k2)*R + lrow], a1 = ew[(2*k2+1)*R + lrow];
        split2(a0, a1, h, l);
        ewth[i] = h; ewtl[i] = l;
    }
}

// ======================= fused per-sample chain kernel (1024 thr) =======================
__device__ __forceinline__ void copyplane(uint32_t* dsth, uint32_t* dstl,
                                          const uint32_t* __restrict__ sh,
                                          const uint32_t* __restrict__ sl) {
    for (int e = threadIdx.x; e < NPAIR; e += CHT) {
        int r = e / 58, c = e - r*58;
        int o = r*CS32 + c;
        dsth[o] = sh[e]; dstl[o] = sl[e];
    }
}

// ldmatrix-based bf16x3 128x128x128 block mma (32 warps, warp tile 16x32)
__device__ __forceinline__ void tc4(uint32_t aAh, uint32_t aAl, uint32_t aBh, uint32_t aBl,
                                    int wr, int wc, int lane, float acc[4][4]) {
    int lrow = lane & 15, lh = lane >> 4;
    #pragma unroll
    for (int kk = 0; kk < 8; kk++) {
        uint32_t kbyt = (uint32_t)(kk * 8) * 4;
        uint32_t ah[4], al[4];
        {
            uint32_t off = (uint32_t)((wr + lrow)*CS32 + lh*4)*4 + kbyt;
            ldsm4(ah[0], ah[1], ah[2], ah[3], aAh + off);
            ldsm4(al[0], al[1], al[2], al[3], aAl + off);
        }
        #pragma unroll
        for (int jb = 0; jb < 2; jb++) {
            uint32_t off = (uint32_t)((wc + 16*jb + lrow)*CS32 + lh*4)*4 + kbyt;
            uint32_t h0,h1,h2,h3, l0,l1,l2,l3;
            ldsm4(h0, h1, h2, h3, aBh + off);
            ldsm4(l0, l1, l2, l3, aBl + off);
            uint32_t bh0[2] = {h0, h2}, bh1[2] = {h1, h3};
            uint32_t bl0[2] = {l0, l2}, bl1[2] = {l1, l3};
            int j0 = 2*jb, j1 = 2*jb + 1;
            mma16816(acc[j0], ah, bh0); mma16816(acc[j1], ah, bh1);
            mma16816(acc[j0], ah, bl0); mma16816(acc[j1], ah, bl1);
            mma16816(acc[j0], al, bh0); mma16816(acc[j1], al, bh1);
        }
    }
}

__device__ __forceinline__ void zacc(float acc[4][4]) {
    #pragma unroll
    for (int j = 0; j < 4; j++)
        #pragma unroll
        for (int q = 0; q < 4; q++) acc[j][q] = 0.f;
}

__device__ __forceinline__ void wtile(const float acc[4][4], uint32_t* Ph, uint32_t* Pl,
                                      const float* __restrict__ bv, int wr, int wc, int lane) {
    int lr = lane >> 2, lc = lane & 3;
    int r0 = wr + lr;
    #pragma unroll
    for (int j = 0; j < 4; j++) {
        int col = wc + 8*j + 2*lc;
        bool cok = col < R;
        float b0 = 0.f, b1v = 0.f;
        if (bv && cok) { b0 = bv[col]; b1v = bv[col+1]; }
        float v0 = (cok && r0   < R) ? acc[j][0] + b0  : 0.f;
        float v1 = (cok && r0   < R) ? acc[j][1] + b1v : 0.f;
        float v2 = (cok && r0+8 < R) ? acc[j][2] + b0  : 0.f;
        float v3 = (cok && r0+8 < R) ? acc[j][3] + b1v : 0.f;
        uint32_t h, l;
        split2(v0, v1, h, l); Ph[r0*CS32 + (col>>1)] = h; Pl[r0*CS32 + (col>>1)] = l;
        split2(v2, v3, h, l); Ph[(r0+8)*CS32 + (col>>1)] = h; Pl[(r0+8)*CS32 + (col>>1)] = l;
    }
}

__global__ void __launch_bounds__(CHT, 1)
k_chain(const uint32_t* __restrict__ Zh_g, const uint32_t* __restrict__ Zl_g,
        const float* __restrict__ Xg,
        const float* __restrict__ w1, const float* __restrict__ b1,
        const uint32_t* __restrict__ W2h, const uint32_t* __restrict__ W2l,
        const float* __restrict__ b2, const float* __restrict__ nw,
        const uint32_t* __restrict__ EwTh, const uint32_t* __restrict__ EwTl,
        float* __restrict__ Z2g, float* __restrict__ X1g) {
    extern __shared__ uint32_t sm[];
    uint32_t* sZh = sm;          uint32_t* sZl = sm + CPL;
    uint32_t* sBh = sm + 2*CPL;  uint32_t* sBl = sm + 3*CPL;
    uint32_t* sCh = sm + 4*CPL;  uint32_t* sCl = sm + 5*CPL;
    float* Sf = (float*)(sm + 4*CPL);
    __shared__ float sX[NF], sk[3*R], sA1[NF];

    int tid = threadIdx.x, lane = tid & 31, w = tid >> 5;
    int wr = (w & 7) * 16, wc = (w >> 3) * 32;
    size_t n = blockIdx.x;

    uint32_t uS = smem_u32(sm);
    uint32_t uZh = uS,            uZl = uS + CPL*4;
    uint32_t uBh = uS + 2*CPL*4,  uBl = uS + 3*CPL*4;
    uint32_t uCh = uS + 4*CPL*4,  uCl = uS + 5*CPL*4;

    for (int i = tid; i < 1464; i += CHT) {
        int r, wcd;
        if (i < 696) { r = i / 6; wcd = 58 + (i - r*6); }
        else { int j = i - 696; r = 116 + (j >> 6); wcd = j & 63; }
        int o = r*CS32 + wcd;
        sZh[o] = 0; sZl[o] = 0; sBh[o] = 0; sBl[o] = 0;
    }
    copyplane(sZh, sZl, Zh_g + n*NPAIR, Zl_g + n*NPAIR);
    copyplane(sBh, sBl, W2h, W2l);
    for (int e = tid; e < NF; e += CHT) sX[e] = Xg[n*(size_t)NF + e];
    __syncthreads();

    for (int e = tid; e < 3*R; e += CHT) {
        int c = e / R, l = e - c*R;
        sk[c*R + l] = b1[c] + w1[c*3]*sX[l*3] + w1[c*3+1]*sX[l*3+1] + w1[c*3+2]*sX[l*3+2];
    }
    __syncthreads();
    for (int e = tid; e < RR; e += CHT) {
        int l = e / R, m = e - l*R;
        Sf[l*117 + m] = sk[l]*sk[m] + sk[R+l]*sk[R+m] + sk[2*R+l]*sk[2*R+m];
    }
    __syncthreads();

    // mma1: ZW = Z @ W2^T
    float acc[4][4];
    zacc(acc);
    tc4(uZh, uZl, uBh, uBl, wr, wc, lane, acc);
    __syncthreads();

    // softmax(S) -> att into sB
    for (int l = w; l < R; l += 32) {
        const float* Srow = Sf + l*117;
        bool sec = lane < 26;
        float a0 = Srow[2*lane], a1 = Srow[2*lane+1];
        float a2 = sec ? Srow[64+2*lane] : -1e30f;
        float a3 = sec ? Srow[65+2*lane] : -1e30f;
        float mx = fmaxf(fmaxf(a0, a1), fmaxf(a2, a3));
        #pragma unroll
        for (int o = 16; o; o >>= 1) mx = fmaxf(mx, __shfl_xor_sync(0xffffffffu, mx, o));
        float e0 = expf(a0-mx), e1 = expf(a1-mx);
        float e2 = sec ? expf(a2-mx) : 0.f, e3 = sec ? expf(a3-mx) : 0.f;
        float sum = e0+e1+e2+e3;
        #pragma unroll
        for (int o = 16; o; o >>= 1) sum += __shfl_xor_sync(0xffffffffu, sum, o);
        float inv = 1.f / sum;
        uint32_t h, lo;
        split2(e0*inv, e1*inv, h, lo);
        sBh[l*CS32 + lane] = h; sBl[l*CS32 + lane] = lo;
        if (sec) {
            split2(e2*inv, e3*inv, h, lo);
            sBh[l*CS32 + 32+lane] = h; sBl[l*CS32 + 32+lane] = lo;
        }
    }
    __syncthreads();

    // ZW (+conv2_b) -> sC
    wtile(acc, sCh, sCl, b2, wr, wc, lane);
    __syncthreads();

    // mma2: P = ZW @ att^T
    zacc(acc);
    tc4(uCh, uCl, uBh, uBl, wr, wc, lane, acc);
    __syncthreads();

    // P -> sC ; transpose Z -> sB
    wtile(acc, sCh, sCl, (const float*)0, wr, wc, lane);
    {
        const __nv_bfloat16* zh = (const __nv_bfloat16*)sZh;
        const __nv_bfloat16* zl = (const __nv_bfloat16*)sZl;
        __nv_bfloat16* bh = (__nv_bfloat16*)sBh;
        __nv_bfloat16* bl = (__nv_bfloat16*)sBl;
        for (int e = tid; e < RR; e += CHT) {
            int k = e / R, j = e - k*R;
            bh[k*136 + j] = zh[j*136 + k];
            bl[k*136 + j] = zl[j*136 + k];
        }
    }
    __syncthreads();

    // mma3: T = P @ Zt^T
    float accT[4][4];
    zacc(accT);
    tc4(uCh, uCl, uBh, uBl, wr, wc, lane, accT);

    // X1 stage1: A1 = P @ X (P in sC)
    if (tid < NF) {
        int m = tid / 3, f = tid - m*3;
        float a = 0.f;
        for (int p = 0; p < 58; p++) {
            uint32_t hw = sCh[m*CS32 + p], lw = sCl[m*CS32 + p];
            __nv_bfloat162 hb = *reinterpret_cast<__nv_bfloat162*>(&hw);
            __nv_bfloat162 lb = *reinterpret_cast<__nv_bfloat162*>(&lw);
            float p0 = __low2float(hb) + __low2float(lb);
            float p1 = __high2float(hb) + __high2float(lb);
            a += p0 * sX[(2*p)*3 + f] + p1 * sX[(2*p+1)*3 + f];
        }
        sA1[tid] = a;
    }
    __syncthreads();

    if (tid < NF) {
        int m = tid / 3, l = tid - m*3;
        X1g[n*(size_t)NF + tid] = sA1[m*3]*nw[l] + sA1[m*3+1]*nw[3+l] + sA1[m*3+2]*nw[6+l];
    }
    wtile(accT, sCh, sCl, (const float*)0, wr, wc, lane);
    copyplane(sBh, sBl, EwTh, EwTl);
    __syncthreads();

    // mma4: Z2 = T @ EwT^T
    zacc(acc);
    tc4(uCh, uCl, uBh, uBl, wr, wc, lane, acc);

    float* out = Z2g + n*(size_t)RR;
    int lr = lane >> 2, lc = lane & 3;
    int r0 = wr + lr;
    #pragma unroll
    for (int j = 0; j < 4; j++) {
        int col = wc + 8*j + 2*lc;
        if (col >= R) continue;
        if (r0 < R) {
            out[r0*R + col]   = acc[j][0];
            out[r0*R + col+1] = acc[j][1];
        }
        if (r0 + 8 < R) {
            out[(r0+8)*R + col]   = acc[j][2];
            out[(r0+8)*R + col+1] = acc[j][3];
        }
    }
}

// ---------------- pre-split big GEMM (headZ, split-K, K-stage=32): C_partial = A @ B^T ----------------
__global__ void __launch_bounds__(256, 2)
k_tc_pre(const uint32_t* __restrict__ Ah_g, const uint32_t* __restrict__ Al_g,
         const uint32_t* __restrict__ Bh_g, const uint32_t* __restrict__ Bl_g,
         float* __restrict__ C, int M, int N, int K2, int kChunk2) {
    extern __shared__ uint32_t sm[];
    int tid = threadIdx.x, lane = tid & 31, w = tid >> 5;
    int warpRow = (w & 3) * 32, warpCol = (w >> 2) * 64;
    int bm = blockIdx.y * 128, bn = blockIdx.x * 128;
    int kb = blockIdx.z * kChunk2;
    int ke = min(kb + kChunk2, K2);
    int nst = (ke - kb + 15) / 16;

    float acc[2][8][4];
    #pragma unroll
    for (int mi = 0; mi < 2; mi++)
        #pragma unroll
        for (int j = 0; j < 8; j++)
            #pragma unroll
            for (int q = 0; q < 4; q++) acc[mi][j][q] = 0.f;

    int r0t = tid >> 2;
    int c4 = (tid & 3) * 4;

    uint4 vah[2], val_[2], vbh[2], vbl[2];
    auto ldt = [&](int s) {
        int ku = kb + s*16 + c4;
        bool ok = (ku + 4) <= ke;
        const uint4 z4 = make_uint4(0,0,0,0);
        #pragma unroll
        for (int q = 0; q < 2; q++) {
            int r = r0t + 64*q;
            size_t ao = (size_t)(bm + r) * K2 + ku;
            size_t bo = (size_t)(bn + r) * K2 + ku;
            vah[q] = ok ? *(const uint4*)(Ah_g + ao) : z4;
            val_[q] = ok ? *(const uint4*)(Al_g + ao) : z4;
            vbh[q] = ok ? *(const uint4*)(Bh_g + bo) : z4;
            vbl[q] = ok ? *(const uint4*)(Bl_g + bo) : z4;
        }
    };
    auto stt = [&](int buf) {
        uint32_t* Ah = sm + buf*4*BPL;
        uint32_t* Al = Ah + BPL;
        uint32_t* Bh = Ah + 2*BPL;
        uint32_t* Bl = Ah + 3*BPL;
        #pragma unroll
        for (int q = 0; q < 2; q++) {
            int r = r0t + 64*q;
            *(uint4*)(Ah + r*BS32 + c4) = vah[q];
            *(uint4*)(Al + r*BS32 + c4) = val_[q];
            *(uint4*)(Bh + r*BS32 + c4) = vbh[q];
            *(uint4*)(Bl + r*BS32 + c4) = vbl[q];
        }
    };

    ldt(0); stt(0);
    __syncthreads();
    for (int s = 0; s < nst; s++) {
        if (s + 1 < nst) ldt(s + 1);
        const uint32_t* base = sm + (s & 1) * 4 * BPL;
        {
            const uint32_t* Ah = base; const uint32_t* Al = base + BPL;
            const uint32_t* Bh = base + 2*BPL; const uint32_t* Bl = base + 3*BPL;
            int lr = lane >> 2, lc = lane & 3;
            for (int kk = 0; kk < 2; kk++) {
                int kp = kk*8 + lc;
                uint32_t ah[2][4], al[2][4];
                #pragma unroll
                for (int mi = 0; mi < 2; mi++) {
                    int r = warpRow + 16*mi + lr;
                    ah[mi][0] = Ah[r*BS32+kp];     ah[mi][1] = Ah[(r+8)*BS32+kp];
                    ah[mi][2] = Ah[r*BS32+kp+4];   ah[mi][3] = Ah[(r+8)*BS32+kp+4];
                    al[mi][0] = Al[r*BS32+kp];     al[mi][1] = Al[(r+8)*BS32+kp];
                    al[mi][2] = Al[r*BS32+kp+4];   al[mi][3] = Al[(r+8)*BS32+kp+4];
                }
                #pragma unroll
                for (int j = 0; j < 8; j++) {
                    int nr = warpCol + 8*j + lr;
                    uint32_t bh[2] = {Bh[nr*BS32+kp], Bh[nr*BS32+kp+4]};
                    uint32_t bl[2] = {Bl[nr*BS32+kp], Bl[nr*BS32+kp+4]};
                    mma16816(acc[0][j], ah[0], bh);
                    mma16816(acc[1][j], ah[1], bh);
                    mma16816(acc[0][j], ah[0], bl);
                    mma16816(acc[1][j], ah[1], bl);
                    mma16816(acc[0][j], al[0], bh);
                    mma16816(acc[1][j], al[1], bh);
                }
            }
        }
        if (s + 1 < nst) stt((s + 1) & 1);
        __syncthreads();
    }

    int lr = lane >> 2, lc = lane & 3;
    float* Cp = C + (size_t)blockIdx.z * M * N;
    #pragma unroll
    for (int mi = 0; mi < 2; mi++) {
        int row0 = bm + warpRow + 16*mi + lr;
        #pragma unroll
        for (int j = 0; j < 8; j++) {
            int col = bn + warpCol + 8*j + 2*lc;
            if (col >= N) continue;
            Cp[(size_t)row0*N + col]     = acc[mi][j][0];
            Cp[(size_t)row0*N + col + 1] = acc[mi][j][1];
            Cp[(size_t)(row0+8)*N + col]     = acc[mi][j][2];
            Cp[(size_t)(row0+8)*N + col + 1] = acc[mi][j][3];
        }
    }
}

// ---------------- fp32-input big GEMM (c1): C = relu(A @ B^T + bias) ----------------
__global__ void __launch_bounds__(256)
k_tc_big(const float* __restrict__ A, const float* __restrict__ B,
         const float* __restrict__ bias, float* __restrict__ C,
         int M, int N, int K) {
    extern __shared__ uint32_t sm[];
    int tid = threadIdx.x, lane = tid & 31, w = tid >> 5;
    int warpRow = (w & 3) * 32, warpCol = (w >> 2) * 64;
    int bm = blockIdx.y * 128, bn = blockIdx.x * 128;
    int nst = (K + 31) / 32;

    float acc[2][8][4];
    #pragma unroll
    for (int mi = 0; mi < 2; mi++)
        #pragma unroll
        for (int j = 0; j < 8; j++)
            #pragma unroll
            for (int q = 0; q < 4; q++) acc[mi][j][q] = 0.f;

    int rA = tid >> 3;
    int cG = (tid & 7) * 4;

    auto ldtile = [&](int s, float4* va, float4* vb) {
        int k0 = s*32 + cG;
        bool kok = (k0 + 4 <= K);
        #pragma unroll
        for (int q = 0; q < 4; q++) {
            const float* ap = A + (size_t)(bm + rA + 32*q) * K;
            va[q] = kok ? *(const float4*)(ap + k0) : make_float4(0.f,0.f,0.f,0.f);
            int br = bn + rA + 32*q;
            const float* bp = B + (size_t)br * K;
            vb[q] = (kok && br < N) ? *(const float4*)(bp + k0) : make_float4(0.f,0.f,0.f,0.f);
        }
    };
    auto sttile = [&](int buf, const float4* va, const float4* vb) {
        uint32_t* Ah = sm + buf*4*BPL;
        uint32_t* Al = Ah + BPL;
        uint32_t* Bh = Ah + 2*BPL;
        uint32_t* Bl = Ah + 3*BPL;
        int kp = cG >> 1;
        #pragma unroll
        for (int q = 0; q < 4; q++) {
            int r = rA + 32*q;
            uint32_t h, l;
            split2(va[q].x, va[q].y, h, l); Ah[r*BS32+kp]   = h; Al[r*BS32+kp]   = l;
            split2(va[q].z, va[q].w, h, l); Ah[r*BS32+kp+1] = h; Al[r*BS32+kp+1] = l;
            split2(vb[q].x, vb[q].y, h, l); Bh[r*BS32+kp]   = h; Bl[r*BS32+kp]   = l;
            split2(vb[q].z, vb[q].w, h, l); Bh[r*BS32+kp+1] = h; Bl[r*BS32+kp+1] = l;
        }
    };

    {
        float4 va[4], vb[4];
        ldtile(0, va, vb);
        sttile(0, va, vb);
    }
    __syncthreads();
    for (int s = 0; s < nst; s++) {
        float4 va[4], vb[4];
        if (s + 1 < nst) ldtile(s + 1, va, vb);
        const uint32_t* base = sm + (s & 1) * 4 * BPL;
        {
            const uint32_t* Ah = base; const uint32_t* Al = base + BPL;
            const uint32_t* Bh = base + 2*BPL; const uint32_t* Bl = base + 3*BPL;
            int lr = lane >> 2, lc = lane & 3;
            for (int kk = 0; kk < 2; kk++) {
                int kp = kk*8 + lc;
                uint32_t ah[2][4], al[2][4];
                #pragma unroll
                for (int mi = 0; mi < 2; mi++) {
                    int r = warpRow + 16*mi + lr;
                    ah[mi][0] = Ah[r*BS32+kp];     ah[mi][1] = Ah[(r+8)*BS32+kp];
                    ah[mi][2] = Ah[r*BS32+kp+4];   ah[mi][3] = Ah[(r+8)*BS32+kp+4];
                    al[mi][0] = Al[r*BS32+kp];     al[mi][1] = Al[(r+8)*BS32+kp];
                    al[mi][2] = Al[r*BS32+kp+4];   al[mi][3] = Al[(r+8)*BS32+kp+4];
                }
                #pragma unroll
                for (int j = 0; j < 8; j++) {
                    int nr = warpCol + 8*j + lr;
                    uint32_t bh[2] = {Bh[nr*BS32+kp], Bh[nr*BS32+kp+4]};
                    uint32_t bl[2] = {Bl[nr*BS32+kp], Bl[nr*BS32+kp+4]};
                    mma16816(acc[0][j], ah[0], bh);
                    mma16816(acc[1][j], ah[1], bh);
                    mma16816(acc[0][j], ah[0], bl);
                    mma16816(acc[1][j], ah[1], bl);
                    mma16816(acc[0][j], al[0], bh);
                    mma16816(acc[1][j], al[1], bh);
                }
            }
        }
        if (s + 1 < nst) sttile((s + 1) & 1, va, vb);
        __syncthreads();
    }

    int lr = lane >> 2, lc = lane & 3;
    #pragma unroll
    for (int mi = 0; mi < 2; mi++) {
        int row0 = bm + warpRow + 16*mi + lr;
        #pragma unroll
        for (int j = 0; j < 8; j++) {
            int col = bn + warpCol + 8*j + 2*lc;
            if (col >= N) continue;
            float b0 = bias[col], b1 = bias[col+1];
            float v0 = fmaxf(acc[mi][j][0] + b0, 0.f), v1 = fmaxf(acc[mi][j][1] + b1, 0.f);
            float v2 = fmaxf(acc[mi][j][2] + b0, 0.f), v3 = fmaxf(acc[mi][j][3] + b1, 0.f);
            C[(size_t)row0*N + col]     = v0;
            C[(size_t)row0*N + col + 1] = v1;
            C[(size_t)(row0+8)*N + col]     = v2;
            C[(size_t)(row0+8)*N + col + 1] = v3;
        }
    }
}

// ---------------- misc kernels ----------------
__global__ void k_copy(float* __restrict__ dst, const float* __restrict__ src, size_t n) {
    size_t i = (size_t)blockIdx.x * blockDim.x + threadIdx.x;
    if (i < n) dst[i] = src[i];
}

// two-phase channel stats for LD=R (Z2)
__global__ void k_chanpart(const float* __restrict__ src, double* __restrict__ ps) {
    int ch = blockIdx.x, slab = blockIdx.y, tid = threadIdx.x;
    int nPer = NB / SLABS;
    int n0 = slab * nPer;
    double s = 0.0, q = 0.0;
    for (int e = tid; e < nPer * R; e += 256) {
        int n = n0 + e / R, l = e - (e / R) * R;
        double v = (double)src[(size_t)n*RR + (size_t)ch*R + l];
        s += v; q += v*v;
    }
    __shared__ double shs[256], shq[256];
    shs[tid] = s; shq[tid] = q;
    __syncthreads();
    for (int o = 128; o > 0; o >>= 1) {
        if (tid < o) { shs[tid] += shs[tid+o]; shq[tid] += shq[tid+o]; }
        __syncthreads();
    }
    if (tid == 0) {
        ps[(ch*SLABS + slab)*2]     = shs[0];
        ps[(ch*SLABS + slab)*2 + 1] = shq[0];
    }
}

__global__ void k_chanfin(const double* __restrict__ ps,
                          float* __restrict__ mean, float* __restrict__ rstd) {
    int ch = threadIdx.x;
    if (ch < R) {
        double s = 0.0, q = 0.0;
        #pragma unroll
        for (int k = 0; k < SLABS; k++) {
            s += ps[(ch*SLABS + k)*2];
            q += ps[(ch*SLABS + k)*2 + 1];
        }
        double tot = (double)NB * R;
        double m = s / tot;
        double var = q / tot - m*m;
        mean[ch] = (float)m;
        rstd[ch] = rsqrtf((float)var + EPSBN);
    }
}

__global__ void k_chanstats(const float* __restrict__ src, int LD,
                            float* __restrict__ mean, float* __restrict__ rstd) {
    int i = blockIdx.x, tid = threadIdx.x;
    int tot = NB * LD;
    double s = 0.0, q = 0.0;
    for (int e = tid; e < tot; e += blockDim.x) {
        int n = e / LD, l = e % LD;
        double v = (double)src[(size_t)n*(R*LD) + (size_t)i*LD + l];
        s += v; q += v*v;
    }
    __shared__ double shs[256], shq[256];
    shs[tid] = s; shq[tid] = q;
    __syncthreads();
    for (int o = blockDim.x >> 1; o > 0; o >>= 1) {
        if (tid < o) { shs[tid] += shs[tid+o]; shq[tid] += shq[tid+o]; }
        __syncthreads();
    }
    if (tid == 0) {
        double m = shs[0] / tot;
        double var = shq[0] / tot - m*m;
        mean[i] = (float)m;
        rstd[i] = rsqrtf((float)var + EPSBN);
    }
}

__global__ void k_updateZ(float* __restrict__ buf, const float* __restrict__ src,
                          const float* __restrict__ mean, const float* __restrict__ rstd,
                          const float* __restrict__ gg, const float* __restrict__ bb,
                          uint32_t* __restrict__ zh, uint32_t* __restrict__ zl) {
    size_t idx2 = (size_t)blockIdx.x * blockDim.x + threadIdx.x;
    if (idx2 >= (size_t)NB*NPAIR) return;
    int p = (int)(idx2 % NPAIR);
    int i = p / 58;
    float2 s2 = ((const float2*)src)[idx2];
    float2 z2 = ((float2*)buf)[idx2];
    float m = mean[i], rs = rstd[i], ga = gg[i], be = bb[i];
    float v0 = (s2.x - m)*rs*ga + be;
    float v1 = (s2.y - m)*rs*ga + be;
    z2.x += fmaxf(v0, 0.f);
    z2.y += fmaxf(v1, 0.f);
    ((float2*)buf)[idx2] = z2;
    uint32_t h, l; split2(z2.x, z2.y, h, l);
    zh[idx2] = h; zl[idx2] = l;
}

__global__ void k_update(float* __restrict__ buf, const float* __restrict__ src, int LD,
                         const float* __restrict__ mean, const float* __restrict__ rstd,
                         const float* __restrict__ g, const float* __restrict__ b) {
    size_t idx = (size_t)blockIdx.x * blockDim.x + threadIdx.x;
    size_t tot = (size_t)NB * R * LD;
    if (idx < tot) {
        int i = (int)((idx / LD) % R);
        float v = (src[idx] - mean[i]) * rstd[i] * g[i] + b[i];
        buf[idx] += fmaxf(v, 0.f);
    }
}

__global__ void __launch_bounds__(256)
k_gemm(const float* __restrict__ A, const float* __restrict__ W,
       const float* __restrict__ bias, float* __restrict__ Cm,
       int M, int Nc, int K) {
    __shared__ float sA[16][68];
    __shared__ float sB[16][68];
    int tid = threadIdx.x;
    int tx = tid & 15, ty = tid >> 4;
    int bm = blockIdx.y * 64, bn = blockIdx.x * 64;
    float acc[4][4];
    #pragma unroll
    for (int i = 0; i < 4; i++)
        #pragma unroll
        for (int j = 0; j < 4; j++) acc[i][j] = 0.f;

    for (int k0 = 0; k0 < K; k0 += 16) {
        #pragma unroll
        for (int q = 0; q < 4; q++) {
            int e = tid + 256*q;
            int r = e >> 4, c = e & 15;
            int gc = k0 + c;
            float av = 0.f, wv = 0.f;
            if (gc < K) {
                av = A[(size_t)(bm + r) * K + gc];
                wv = W[(size_t)(bn + r) * K + gc];
            }
            sA[c][r] = av;
            sB[c][r] = wv;
        }
        __syncthreads();
        #pragma unroll
        for (int kk = 0; kk < 16; kk++) {
            float4 a4 = *(const float4*)&sA[kk][ty*4];
            float4 b4 = *(const float4*)&sB[kk][tx*4];
            float a[4] = {a4.x, a4.y, a4.z, a4.w};
            float b[4] = {b4.x, b4.y, b4.z, b4.w};
            #pragma unroll
            for (int i = 0; i < 4; i++)
                #pragma unroll
                for (int j = 0; j < 4; j++) acc[i][j] += a[i]*b[j];
        }
        __syncthreads();
    }
    #pragma unroll
    for (int i = 0; i < 4; i++) {
        int row = bm + ty*4 + i;
        #pragma unroll
        for (int j = 0; j < 4; j++) {
            int col = bn + tx*4 + j;
            float v = acc[i][j] + bias[col];
            v = fmaxf(v, 0.f);
            Cm[(size_t)row * Nc + col] = v;
        }
    }
}

__global__ void k_colstats(const float* __restrict__ Y, int C,
                           float* __restrict__ mean, float* __restrict__ rstd) {
    int c = blockIdx.x, tid = threadIdx.x;
    double s = 0.0, q = 0.0;
    for (int r = tid; r < NB; r += blockDim.x) {
        double v = (double)Y[(size_t)r*C + c];
        s += v; q += v*v;
    }
    __shared__ double shs[256], shq[256];
    shs[tid] = s; shq[tid] = q;
    __syncthreads();
    for (int o = blockDim.x >> 1; o > 0; o >>= 1) {
        if (tid < o) { shs[tid] += shs[tid+o]; shq[tid] += shq[tid+o]; }
        __syncthreads();
    }
    if (tid == 0) {
        double m = shs[0] / NB;
        double var = shq[0] / NB - m*m;
        mean[c] = (float)m;
        rstd[c] = rsqrtf((float)var + EPSBN);
    }
}

__global__ void k_bnapply(const float* __restrict__ Y, int C, int off,
                          const float* __restrict__ mean, const float* __restrict__ rstd,
                          const float* __restrict__ g, const float* __restrict__ b,
                          float* __restrict__ XZ) {
    int idx = blockIdx.x * blockDim.x + threadIdx.x;
    if (idx < NB * C) {
        int r = idx / C, c = idx % C;
        XZ[(size_t)r*CC + off + c] = (Y[idx] - mean[c]) * rstd[c] * g[c] + b[c];
    }
}

__global__ void k_redz(const float* __restrict__ parts, const float* __restrict__ bias,
                       float* __restrict__ out) {
    int idx = blockIdx.x * blockDim.x + threadIdx.x;
    if (idx < NB * H3) {
        int c = idx % H3;
        float s = bias[c];
        #pragma unroll
        for (int k = 0; k < SPLITS; k++) s += parts[(size_t)k*NB*H3 + idx];
        out[idx] = fmaxf(s, 0.f);
    }
}

__global__ void k_c2(const float* __restrict__ hbuf, const float* __restrict__ w,
                     const float* __restrict__ b, float* __restrict__ out) {
    int gw = (blockIdx.x * blockDim.x + threadIdx.x) >> 5;
    int lane = threadIdx.x & 31;
    if (gw >= NB) return;
    const float* hrow = hbuf + (size_t)gw * C1;
    float s0 = 0.f, s1 = 0.f;
    for (int k = lane; k < C1; k += 32) {
        float hv = hrow[k];
        s0 += hv * w[k];
        s1 += hv * w[C1 + k];
    }
    #pragma unroll
    for (int o = 16; o; o >>= 1) {
        s0 += __shfl_xor_sync(0xffffffffu, s0, o);
        s1 += __shfl_xor_sync(0xffffffffu, s1, o);
    }
    if (lane == 0) { out[gw*2 + 0] = s0 + b[0]; out[gw*2 + 1] = s1 + b[1]; }
}

// ---------------- host ----------------
extern "C" void kernel_launch(void* const* d_in, const int* in_sizes, int n_in,
                              void* d_out, int out_size) {
    const float* Xin     = (const float*)d_in[0];
    const float* Zin     = (const float*)d_in[1];
    const float* conv1_w = (const float*)d_in[2];
    const float* conv1_b = (const float*)d_in[3];
    const float* conv2_w = (const float*)d_in[4];
    const float* conv2_b = (const float*)d_in[5];
    const float* node_w  = (const float*)d_in[6];
    const float* edge_w  = (const float*)d_in[7];
    const float* bn_n_g  = (const float*)d_in[8];
    const float* bn_n_b  = (const float*)d_in[9];
    const float* bn_e_g  = (const float*)d_in[10];
    const float* bn_e_b  = (const float*)d_in[11];
    const float* ln_w    = (const float*)d_in[12];
    const float* ln_b    = (const float*)d_in[13];
    const float* ln_bn_g = (const float*)d_in[14];
    const float* ln_bn_b = (const float*)d_in[15];
    const float* le_w    = (const float*)d_in[16];
    const float* le_b    = (const float*)d_in[17];
    const float* le_bn_g = (const float*)d_in[18];
    const float* le_bn_b = (const float*)d_in[19];
    const float* c1_w    = (const float*)d_in[20];
    const float* c1_b    = (const float*)d_in[21];
    const float* c2_w    = (const float*)d_in[22];
    const float* c2_b    = (const float*)d_in[23];
    float* outp = (float*)d_out;

    float *pX, *pZ, *pZ2, *pX1, *pYx, *pYz, *pYzS, *pXZ, *pH;
    float *pM1, *pR1, *pMz, *pRz, *pMx, *pRx;
    double* pPS;
    uint32_t *pZh, *pZl, *pLWh, *pLWl, *pW2h, *pW2l, *pEwTh, *pEwTl;
    cudaGetSymbolAddress((void**)&pX,   g_X);
    cudaGetSymbolAddress((void**)&pZ,   g_Z);
    cudaGetSymbolAddress((void**)&pZ2,  g_Z2);
    cudaGetSymbolAddress((void**)&pX1,  g_X1);
    cudaGetSymbolAddress((void**)&pYx,  g_Yx);
    cudaGetSymbolAddress((void**)&pYz,  g_Yz);
    cudaGetSymbolAddress((void**)&pYzS, g_YzS);
    cudaGetSymbolAddress((void**)&pXZ,  g_XZ);
    cudaGetSymbolAddress((void**)&pH,   g_Hb);
    cudaGetSymbolAddress((void**)&pZh,  g_Zh);
    cudaGetSymbolAddress((void**)&pZl,  g_Zl);
    cudaGetSymbolAddress((void**)&pLWh, g_LWh);
    cudaGetSymbolAddress((void**)&pLWl, g_LWl);
    cudaGetSymbolAddress((void**)&pW2h, g_W2h);
    cudaGetSymbolAddress((void**)&pW2l, g_W2l);
    cudaGetSymbolAddress((void**)&pEwTh, g_EwTh);
    cudaGetSymbolAddress((void**)&pEwTl, g_EwTl);
    cudaGetSymbolAddress((void**)&pPS,  g_ps);
    cudaGetSymbolAddress((void**)&pM1,  g_m1);
    cudaGetSymbolAddress((void**)&pR1,  g_r1);
    cudaGetSymbolAddress((void**)&pMz,  g_mz);
    cudaGetSymbolAddress((void**)&pRz,  g_rz);
    cudaGetSymbolAddress((void**)&pMx,  g_mx);
    cudaGetSymbolAddress((void**)&pRx,  g_rx);

    cudaFuncSetAttribute(k_chain, cudaFuncAttributeMaxDynamicSharedMemorySize, CH_SMEM);
    cudaFuncSetAttribute(k_tc_pre, cudaFuncAttributeMaxDynamicSharedMemorySize, BIG_SMEM);
    cudaFuncSetAttribute(k_tc_big, cudaFuncAttributeMaxDynamicSharedMemorySize, BIG_SMEM);

    auto chain = [&](int i) {
        k_prep<<<(NPAIR + 255)/256, 256>>>(conv2_w + (size_t)i*RR, edge_w + (size_t)i*RR,
                                           pW2h, pW2l, pEwTh, pEwTl);
        k_chain<<<NB, CHT, CH_SMEM>>>(pZh, pZl, pX,
                                      conv1_w + i*9, conv1_b + i*3,
                                      pW2h, pW2l, conv2_b + i*R,
                                      node_w + i*9, pEwTh, pEwTl, pZ2, pX1);
    };
    auto headZgemm = [&](int i) {
        k_tc_pre<<<dim3(H3/128, NB/128, SPLITS), 256, BIG_SMEM>>>(
            pZh, pZl, pLWh + (size_t)i*H3*NPAIR, pLWl + (size_t)i*H3*NPAIR,
            pYzS, NB, H3, NPAIR, KCHUNK2);
    };
    auto headZpost = [&](int i) {
        k_redz<<<(NB*H3 + 255)/256, 256>>>(pYzS, le_b + i*H3, pYz);
        k_colstats<<<H3, 256>>>(pYz, H3, pM1, pR1);
        k_bnapply<<<(NB*H3 + 255)/256, 256>>>(pYz, H3, 5*H + i*H3, pM1, pR1, le_bn_g + i*H3, le_bn_b + i*H3, pXZ);
    };
    auto headX = [&](int i) {
        k_gemm<<<dim3(H/64, NB/64), 256>>>(pX, ln_w + (size_t)i*H*NF, ln_b + i*H, pYx, NB, H, NF);
        k_colstats<<<H, 256>>>(pYx, H, pM1, pR1);
        k_bnapply<<<(NB*H + 255)/256, 256>>>(pYx, H, i*H, pM1, pR1, ln_bn_g + i*H, ln_bn_b + i*H, pXZ);
    };

    // startup ordered so launch index 3 (0-based) = k_tc_pre (ncu capture slot)
    k_copy<<<(NB*NF + 255)/256, 256>>>(pX, Xin, (size_t)NB*NF);                                    // 0
    k_splitZ0<<<(int)(((size_t)NB*NPAIR + 255)/256), 256>>>(Zin, pZ, pZh, pZl);                    // 1
    k_split<<<(int)(((size_t)5*H3*NPAIR + 255)/256), 256>>>(le_w, pLWh, pLWl, (size_t)5*H3*NPAIR); // 2
    headZgemm(0);                                                                                  // 3 <- profiled
    headZpost(0);
    headX(0);
    chain(0);

    for (int i = 0; i < 4; i++) {
        if (i > 0) chain(i);
        // edge BN stats (two-phase), residual + plane maintenance, then Z head
        k_chanpart<<<dim3(R, SLABS), 256>>>(pZ2, pPS);
        k_chanfin<<<1, 128>>>(pPS, pMz, pRz);
        k_updateZ<<<(int)(((size_t)NB*NPAIR + 255)/256), 256>>>(pZ, pZ2, pMz, pRz,
                                                                bn_e_g + i*R, bn_e_b + i*R, pZh, pZl);
        headZgemm(i + 1);
        headZpost(i + 1);
        // node BN + residual, then X head
        k_chanstats<<<R, 256>>>(pX1, 3, pMx, pRx);
        k_update<<<(NB*NF + 255)/256, 256>>>(pX, pX1, 3, pMx, pRx, bn_n_g + i*R, bn_n_b + i*R);
        headX(i + 1);
    }

    k_tc_big<<<dim3(C1/128, NB/128, 1), 256, BIG_SMEM>>>(pXZ, c1_w, c1_b, pH, NB, C1, CC);
    k_c2<<<NB*32/256, 256>>>(pH, c2_w, c2_b, outp);
}

// round 15
// speedup vs baseline: 1.0314x; 1.0314x over previous
#include <cuda_runtime.h>
#include <cuda_bf16.h>
#include <cstdint>
#include <math.h>

#define NB 2048
#define R 116
#define RR 13456
#define NPAIR 6728
#define NF 348
#define H 128
#define H3 384
#define CC 2560
#define C1 1024
#define EPSBN 1e-5f
#define SPLITS 6
#define KCHUNK2 1136
#define CHT 1024
#define SLABS 8

// big tc kernels: stage K=32 (16 u32), row stride 20 u32
#define BS32 20
#define BPL (128*BS32)
#define BIG_SMEM (2*4*BPL*4)
// fused chain kernel: K=128 padded, row stride 68 u32
#define CS32 68
#define CPL (128*CS32)
#define CH_SMEM (6*CPL*4)

// ---------------- scratch ----------------
static __device__ float g_X [(size_t)NB*NF];
static __device__ float g_Z2[(size_t)NB*RR];
static __device__ float g_X1[(size_t)NB*NF];
static __device__ float g_Yx[(size_t)NB*H];
static __device__ float g_Yz[(size_t)NB*H3];
static __device__ float g_YzS[(size_t)SPLITS*NB*H3];
static __device__ float g_XZ[(size_t)NB*CC];
static __device__ float g_Hb[(size_t)NB*C1];
static __device__ uint32_t g_Zh[(size_t)NB*NPAIR];
static __device__ uint32_t g_Zl[(size_t)NB*NPAIR];
static __device__ uint32_t g_LWh[(size_t)5*H3*NPAIR];
static __device__ uint32_t g_LWl[(size_t)5*H3*NPAIR];
static __device__ uint32_t g_W2h[NPAIR], g_W2l[NPAIR];
static __device__ uint32_t g_EwTh[NPAIR], g_EwTl[NPAIR];
static __device__ double g_ps[R*SLABS*2];
static __device__ float g_m1[H3], g_r1[H3];
static __device__ float g_mz[R], g_rz[R], g_mx[R], g_rx[R];

// ---------------- helpers ----------------
__device__ __forceinline__ void mma16816(float* c, const uint32_t* a, const uint32_t* b) {
    asm volatile(
        "mma.sync.aligned.m16n8k16.row.col.f32.bf16.bf16.f32 "
        "{%0,%1,%2,%3}, {%4,%5,%6,%7}, {%8,%9}, {%0,%1,%2,%3};\n"
        : "+f"(c[0]), "+f"(c[1]), "+f"(c[2]), "+f"(c[3])
        : "r"(a[0]), "r"(a[1]), "r"(a[2]), "r"(a[3]), "r"(b[0]), "r"(b[1]));
}

__device__ __forceinline__ void ldsm4(uint32_t& r0, uint32_t& r1, uint32_t& r2, uint32_t& r3, uint32_t a) {
    asm volatile("ldmatrix.sync.aligned.m8n8.x4.shared.b16 {%0,%1,%2,%3}, [%4];"
        : "=r"(r0), "=r"(r1), "=r"(r2), "=r"(r3) : "r"(a));
}

__device__ __forceinline__ uint32_t smem_u32(const void* p) {
    uint32_t a;
    asm("{ .reg .u64 t; cvta.to.shared.u64 t, %1; cvt.u32.u64 %0, t; }" : "=r"(a) : "l"(p));
    return a;
}

__device__ __forceinline__ void split2(float x0, float x1, uint32_t& hi, uint32_t& lo) {
    __nv_bfloat16 h0 = __float2bfloat16(x0), h1 = __float2bfloat16(x1);
    float r0 = x0 - __bfloat162float(h0), r1 = x1 - __bfloat162float(h1);
    __nv_bfloat16 l0 = __float2bfloat16(r0), l1 = __float2bfloat16(r1);
    hi = (uint32_t)__bfloat16_as_ushort(h0) | ((uint32_t)__bfloat16_as_ushort(h1) << 16);
    lo = (uint32_t)__bfloat16_as_ushort(l0) | ((uint32_t)__bfloat16_as_ushort(l1) << 16);
}

// ---------------- split kernels ----------------
__global__ void k_split(const float* __restrict__ src, uint32_t* __restrict__ dh,
                        uint32_t* __restrict__ dl, size_t npairs) {
    size_t i = (size_t)blockIdx.x * blockDim.x + threadIdx.x;
    if (i < npairs) {
        float2 v = ((const float2*)src)[i];
        uint32_t h, l; split2(v.x, v.y, h, l);
        dh[i] = h; dl[i] = l;
    }
}

__global__ void k_prep(const float* __restrict__ w2, const float* __restrict__ ew,
                       uint32_t* __restrict__ w2h, uint32_t* __restrict__ w2l,
                       uint32_t* __restrict__ ewth, uint32_t* __restrict__ ewtl) {
    int i = blockIdx.x * blockDim.x + threadIdx.x;
    if (i < NPAIR) {
        float2 v = ((const float2*)w2)[i];
        uint32_t h, l; split2(v.x, v.y, h, l);
        w2h[i] = h; w2l[i] = l;
        int lrow = i / 58, k2 = i - lrow*58;
        float a0 = ew[(2*k2)*R + lrow], a1 = ew[(2*k2+1)*R + lrow];
        split2(a0, a1, h, l);
        ewth[i] = h; ewtl[i] = l;
    }
}

// ======================= fused per-sample chain kernel (1024 thr) =======================
__device__ __forceinline__ void copyplane(uint32_t* dsth, uint32_t* dstl,
                                          const uint32_t* __restrict__ sh,
                                          const uint32_t* __restrict__ sl) {
    for (int e = threadIdx.x; e < NPAIR; e += CHT) {
        int r = e / 58, c = e - r*58;
        int o = r*CS32 + c;
        dsth[o] = sh[e]; dstl[o] = sl[e];
    }
}

// ldmatrix-based bf16x3 128x128x128 block mma (32 warps, warp tile 16x32)
__device__ __forceinline__ void tc4(uint32_t aAh, uint32_t aAl, uint32_t aBh, uint32_t aBl,
                                    int wr, int wc, int lane, float acc[4][4]) {
    int lrow = lane & 15, lh = lane >> 4;
    #pragma unroll
    for (int kk = 0; kk < 8; kk++) {
        uint32_t kbyt = (uint32_t)(kk * 8) * 4;
        uint32_t ah[4], al[4];
        {
            uint32_t off = (uint32_t)((wr + lrow)*CS32 + lh*4)*4 + kbyt;
            ldsm4(ah[0], ah[1], ah[2], ah[3], aAh + off);
            ldsm4(al[0], al[1], al[2], al[3], aAl + off);
        }
        #pragma unroll
        for (int jb = 0; jb < 2; jb++) {
            uint32_t off = (uint32_t)((wc + 16*jb + lrow)*CS32 + lh*4)*4 + kbyt;
            uint32_t h0,h1,h2,h3, l0,l1,l2,l3;
            ldsm4(h0, h1, h2, h3, aBh + off);
            ldsm4(l0, l1, l2, l3, aBl + off);
            uint32_t bh0[2] = {h0, h2}, bh1[2] = {h1, h3};
            uint32_t bl0[2] = {l0, l2}, bl1[2] = {l1, l3};
            int j0 = 2*jb, j1 = 2*jb + 1;
            mma16816(acc[j0], ah, bh0); mma16816(acc[j1], ah, bh1);
            mma16816(acc[j0], ah, bl0); mma16816(acc[j1], ah, bl1);
            mma16816(acc[j0], al, bh0); mma16816(acc[j1], al, bh1);
        }
    }
}

__device__ __forceinline__ void zacc(float acc[4][4]) {
    #pragma unroll
    for (int j = 0; j < 4; j++)
        #pragma unroll
        for (int q = 0; q < 4; q++) acc[j][q] = 0.f;
}

__device__ __forceinline__ void wtile(const float acc[4][4], uint32_t* Ph, uint32_t* Pl,
                                      const float* __restrict__ bv, int wr, int wc, int lane) {
    int lr = lane >> 2, lc = lane & 3;
    int r0 = wr + lr;
    #pragma unroll
    for (int j = 0; j < 4; j++) {
        int col = wc + 8*j + 2*lc;
        bool cok = col < R;
        float b0 = 0.f, b1v = 0.f;
        if (bv && cok) { b0 = bv[col]; b1v = bv[col+1]; }
        float v0 = (cok && r0   < R) ? acc[j][0] + b0  : 0.f;
        float v1 = (cok && r0   < R) ? acc[j][1] + b1v : 0.f;
        float v2 = (cok && r0+8 < R) ? acc[j][2] + b0  : 0.f;
        float v3 = (cok && r0+8 < R) ? acc[j][3] + b1v : 0.f;
        uint32_t h, l;
        split2(v0, v1, h, l); Ph[r0*CS32 + (col>>1)] = h; Pl[r0*CS32 + (col>>1)] = l;
        split2(v2, v3, h, l); Ph[(r0+8)*CS32 + (col>>1)] = h; Pl[(r0+8)*CS32 + (col>>1)] = l;
    }
}

__global__ void __launch_bounds__(CHT, 1)
k_chain(const uint32_t* __restrict__ Zh_g, const uint32_t* __restrict__ Zl_g,
        const float* __restrict__ Xg,
        const float* __restrict__ w1, const float* __restrict__ b1,
        const uint32_t* __restrict__ W2h, const uint32_t* __restrict__ W2l,
        const float* __restrict__ b2, const float* __restrict__ nw,
        const uint32_t* __restrict__ EwTh, const uint32_t* __restrict__ EwTl,
        float* __restrict__ Z2g, float* __restrict__ X1g) {
    extern __shared__ uint32_t sm[];
    uint32_t* sZh = sm;          uint32_t* sZl = sm + CPL;
    uint32_t* sBh = sm + 2*CPL;  uint32_t* sBl = sm + 3*CPL;
    uint32_t* sCh = sm + 4*CPL;  uint32_t* sCl = sm + 5*CPL;
    float* Sf = (float*)(sm + 4*CPL);
    __shared__ float sX[NF], sk[3*R], sA1[NF];

    int tid = threadIdx.x, lane = tid & 31, w = tid >> 5;
    int wr = (w & 7) * 16, wc = (w >> 3) * 32;
    size_t n = blockIdx.x;

    uint32_t uS = smem_u32(sm);
    uint32_t uZh = uS,            uZl = uS + CPL*4;
    uint32_t uBh = uS + 2*CPL*4,  uBl = uS + 3*CPL*4;
    uint32_t uCh = uS + 4*CPL*4,  uCl = uS + 5*CPL*4;

    for (int i = tid; i < 1464; i += CHT) {
        int r, wcd;
        if (i < 696) { r = i / 6; wcd = 58 + (i - r*6); }
        else { int j = i - 696; r = 116 + (j >> 6); wcd = j & 63; }
        int o = r*CS32 + wcd;
        sZh[o] = 0; sZl[o] = 0; sBh[o] = 0; sBl[o] = 0;
    }
    copyplane(sZh, sZl, Zh_g + n*NPAIR, Zl_g + n*NPAIR);
    copyplane(sBh, sBl, W2h, W2l);
    for (int e = tid; e < NF; e += CHT) sX[e] = Xg[n*(size_t)NF + e];
    __syncthreads();

    for (int e = tid; e < 3*R; e += CHT) {
        int c = e / R, l = e - c*R;
        sk[c*R + l] = b1[c] + w1[c*3]*sX[l*3] + w1[c*3+1]*sX[l*3+1] + w1[c*3+2]*sX[l*3+2];
    }
    __syncthreads();
    for (int e = tid; e < RR; e += CHT) {
        int l = e / R, m = e - l*R;
        Sf[l*117 + m] = sk[l]*sk[m] + sk[R+l]*sk[R+m] + sk[2*R+l]*sk[2*R+m];
    }
    __syncthreads();

    // mma1: ZW = Z @ W2^T
    float acc[4][4];
    zacc(acc);
    tc4(uZh, uZl, uBh, uBl, wr, wc, lane, acc);
    __syncthreads();

    // softmax(S) -> att into sB
    for (int l = w; l < R; l += 32) {
        const float* Srow = Sf + l*117;
        bool sec = lane < 26;
        float a0 = Srow[2*lane], a1 = Srow[2*lane+1];
        float a2 = sec ? Srow[64+2*lane] : -1e30f;
        float a3 = sec ? Srow[65+2*lane] : -1e30f;
        float mx = fmaxf(fmaxf(a0, a1), fmaxf(a2, a3));
        #pragma unroll
        for (int o = 16; o; o >>= 1) mx = fmaxf(mx, __shfl_xor_sync(0xffffffffu, mx, o));
        float e0 = expf(a0-mx), e1 = expf(a1-mx);
        float e2 = sec ? expf(a2-mx) : 0.f, e3 = sec ? expf(a3-mx) : 0.f;
        float sum = e0+e1+e2+e3;
        #pragma unroll
        for (int o = 16; o; o >>= 1) sum += __shfl_xor_sync(0xffffffffu, sum, o);
        float inv = 1.f / sum;
        uint32_t h, lo;
        split2(e0*inv, e1*inv, h, lo);
        sBh[l*CS32 + lane] = h; sBl[l*CS32 + lane] = lo;
        if (sec) {
            split2(e2*inv, e3*inv, h, lo);
            sBh[l*CS32 + 32+lane] = h; sBl[l*CS32 + 32+lane] = lo;
        }
    }
    __syncthreads();

    // ZW (+conv2_b) -> sC
    wtile(acc, sCh, sCl, b2, wr, wc, lane);
    __syncthreads();

    // mma2: P = ZW @ att^T
    zacc(acc);
    tc4(uCh, uCl, uBh, uBl, wr, wc, lane, acc);
    __syncthreads();

    // P -> sC ; transpose Z -> sB
    wtile(acc, sCh, sCl, (const float*)0, wr, wc, lane);
    {
        const __nv_bfloat16* zh = (const __nv_bfloat16*)sZh;
        const __nv_bfloat16* zl = (const __nv_bfloat16*)sZl;
        __nv_bfloat16* bh = (__nv_bfloat16*)sBh;
        __nv_bfloat16* bl = (__nv_bfloat16*)sBl;
        for (int e = tid; e < RR; e += CHT) {
            int k = e / R, j = e - k*R;
            bh[k*136 + j] = zh[j*136 + k];
            bl[k*136 + j] = zl[j*136 + k];
        }
    }
    __syncthreads();

    // mma3: T = P @ Zt^T
    float accT[4][4];
    zacc(accT);
    tc4(uCh, uCl, uBh, uBl, wr, wc, lane, accT);

    // X1 stage1: A1 = P @ X (P in sC)
    if (tid < NF) {
        int m = tid / 3, f = tid - m*3;
        float a = 0.f;
        for (int p = 0; p < 58; p++) {
            uint32_t hw = sCh[m*CS32 + p], lw = sCl[m*CS32 + p];
            __nv_bfloat162 hb = *reinterpret_cast<__nv_bfloat162*>(&hw);
            __nv_bfloat162 lb = *reinterpret_cast<__nv_bfloat162*>(&lw);
            float p0 = __low2float(hb) + __low2float(lb);
            float p1 = __high2float(hb) + __high2float(lb);
            a += p0 * sX[(2*p)*3 + f] + p1 * sX[(2*p+1)*3 + f];
        }
        sA1[tid] = a;
    }
    __syncthreads();

    if (tid < NF) {
        int m = tid / 3, l = tid - m*3;
        X1g[n*(size_t)NF + tid] = sA1[m*3]*nw[l] + sA1[m*3+1]*nw[3+l] + sA1[m*3+2]*nw[6+l];
    }
    wtile(accT, sCh, sCl, (const float*)0, wr, wc, lane);
    copyplane(sBh, sBl, EwTh, EwTl);
    __syncthreads();

    // mma4: Z2 = T @ EwT^T
    zacc(acc);
    tc4(uCh, uCl, uBh, uBl, wr, wc, lane, acc);

    float* out = Z2g + n*(size_t)RR;
    int lr = lane >> 2, lc = lane & 3;
    int r0 = wr + lr;
    #pragma unroll
    for (int j = 0; j < 4; j++) {
        int col = wc + 8*j + 2*lc;
        if (col >= R) continue;
        if (r0 < R) {
            out[r0*R + col]   = acc[j][0];
            out[r0*R + col+1] = acc[j][1];
        }
        if (r0 + 8 < R) {
            out[(r0+8)*R + col]   = acc[j][2];
            out[(r0+8)*R + col+1] = acc[j][3];
        }
    }
}

// ---------------- pre-split big GEMM (headZ, split-K, K-stage=32): C_partial = A @ B^T ----------------
__global__ void __launch_bounds__(256)
k_tc_pre(const uint32_t* __restrict__ Ah_g, const uint32_t* __restrict__ Al_g,
         const uint32_t* __restrict__ Bh_g, const uint32_t* __restrict__ Bl_g,
         float* __restrict__ C, int M, int N, int K2, int kChunk2) {
    extern __shared__ uint32_t sm[];
    int tid = threadIdx.x, lane = tid & 31, w = tid >> 5;
    int warpRow = (w & 3) * 32, warpCol = (w >> 2) * 64;
    int bm = blockIdx.y * 128, bn = blockIdx.x * 128;
    int kb = blockIdx.z * kChunk2;
    int ke = min(kb + kChunk2, K2);
    int nst = (ke - kb + 15) / 16;

    float acc[2][8][4];
    #pragma unroll
    for (int mi = 0; mi < 2; mi++)
        #pragma unroll
        for (int j = 0; j < 8; j++)
            #pragma unroll
            for (int q = 0; q < 4; q++) acc[mi][j][q] = 0.f;

    int r0t = tid >> 2;
    int c4 = (tid & 3) * 4;

    uint4 vah[2], val_[2], vbh[2], vbl[2];
    auto ldt = [&](int s) {
        int ku = kb + s*16 + c4;
        bool ok = (ku + 4) <= ke;
        const uint4 z4 = make_uint4(0,0,0,0);
        #pragma unroll
        for (int q = 0; q < 2; q++) {
            int r = r0t + 64*q;
            size_t ao = (size_t)(bm + r) * K2 + ku;
            size_t bo = (size_t)(bn + r) * K2 + ku;
            vah[q] = ok ? *(const uint4*)(Ah_g + ao) : z4;
            val_[q] = ok ? *(const uint4*)(Al_g + ao) : z4;
            vbh[q] = ok ? *(const uint4*)(Bh_g + bo) : z4;
            vbl[q] = ok ? *(const uint4*)(Bl_g + bo) : z4;
        }
    };
    auto stt = [&](int buf) {
        uint32_t* Ah = sm + buf*4*BPL;
        uint32_t* Al = Ah + BPL;
        uint32_t* Bh = Ah + 2*BPL;
        uint32_t* Bl = Ah + 3*BPL;
        #pragma unroll
        for (int q = 0; q < 2; q++) {
            int r = r0t + 64*q;
            *(uint4*)(Ah + r*BS32 + c4) = vah[q];
            *(uint4*)(Al + r*BS32 + c4) = val_[q];
            *(uint4*)(Bh + r*BS32 + c4) = vbh[q];
            *(uint4*)(Bl + r*BS32 + c4) = vbl[q];
        }
    };

    ldt(0); stt(0);
    __syncthreads();
    for (int s = 0; s < nst; s++) {
        if (s + 1 < nst) ldt(s + 1);
        const uint32_t* base = sm + (s & 1) * 4 * BPL;
        {
            const uint32_t* Ah = base; const uint32_t* Al = base + BPL;
            const uint32_t* Bh = base + 2*BPL; const uint32_t* Bl = base + 3*BPL;
            int lr = lane >> 2, lc = lane & 3;
            for (int kk = 0; kk < 2; kk++) {
                int kp = kk*8 + lc;
                uint32_t ah[2][4], al[2][4];
                #pragma unroll
                for (int mi = 0; mi < 2; mi++) {
                    int r = warpRow + 16*mi + lr;
                    ah[mi][0] = Ah[r*BS32+kp];     ah[mi][1] = Ah[(r+8)*BS32+kp];
                    ah[mi][2] = Ah[r*BS32+kp+4];   ah[mi][3] = Ah[(r+8)*BS32+kp+4];
                    al[mi][0] = Al[r*BS32+kp];     al[mi][1] = Al[(r+8)*BS32+kp];
                    al[mi][2] = Al[r*BS32+kp+4];   al[mi][3] = Al[(r+8)*BS32+kp+4];
                }
                #pragma unroll
                for (int j = 0; j < 8; j++) {
                    int nr = warpCol + 8*j + lr;
                    uint32_t bh[2] = {Bh[nr*BS32+kp], Bh[nr*BS32+kp+4]};
                    uint32_t bl[2] = {Bl[nr*BS32+kp], Bl[nr*BS32+kp+4]};
                    mma16816(acc[0][j], ah[0], bh);
                    mma16816(acc[1][j], ah[1], bh);
                    mma16816(acc[0][j], ah[0], bl);
                    mma16816(acc[1][j], ah[1], bl);
                    mma16816(acc[0][j], al[0], bh);
                    mma16816(acc[1][j], al[1], bh);
                }
            }
        }
        if (s + 1 < nst) stt((s + 1) & 1);
        __syncthreads();
    }

    int lr = lane >> 2, lc = lane & 3;
    float* Cp = C + (size_t)blockIdx.z * M * N;
    #pragma unroll
    for (int mi = 0; mi < 2; mi++) {
        int row0 = bm + warpRow + 16*mi + lr;
        #pragma unroll
        for (int j = 0; j < 8; j++) {
            int col = bn + warpCol + 8*j + 2*lc;
            if (col >= N) continue;
            Cp[(size_t)row0*N + col]     = acc[mi][j][0];
            Cp[(size_t)row0*N + col + 1] = acc[mi][j][1];
            Cp[(size_t)(row0+8)*N + col]     = acc[mi][j][2];
            Cp[(size_t)(row0+8)*N + col + 1] = acc[mi][j][3];
        }
    }
}

// ---------------- fp32-input big GEMM (c1): C = relu(A @ B^T + bias) ----------------
__global__ void __launch_bounds__(256)
k_tc_big(const float* __restrict__ A, const float* __restrict__ B,
         const float* __restrict__ bias, float* __restrict__ C,
         int M, int N, int K) {
    extern __shared__ uint32_t sm[];
    int tid = threadIdx.x, lane = tid & 31, w = tid >> 5;
    int warpRow = (w & 3) * 32, warpCol = (w >> 2) * 64;
    int bm = blockIdx.y * 128, bn = blockIdx.x * 128;
    int nst = (K + 31) / 32;

    float acc[2][8][4];
    #pragma unroll
    for (int mi = 0; mi < 2; mi++)
        #pragma unroll
        for (int j = 0; j < 8; j++)
            #pragma unroll
            for (int q = 0; q < 4; q++) acc[mi][j][q] = 0.f;

    int rA = tid >> 3;
    int cG = (tid & 7) * 4;

    auto ldtile = [&](int s, float4* va, float4* vb) {
        int k0 = s*32 + cG;
        bool kok = (k0 + 4 <= K);
        #pragma unroll
        for (int q = 0; q < 4; q++) {
            const float* ap = A + (size_t)(bm + rA + 32*q) * K;
            va[q] = kok ? *(const float4*)(ap + k0) : make_float4(0.f,0.f,0.f,0.f);
            int br = bn + rA + 32*q;
            const float* bp = B + (size_t)br * K;
            vb[q] = (kok && br < N) ? *(const float4*)(bp + k0) : make_float4(0.f,0.f,0.f,0.f);
        }
    };
    auto sttile = [&](int buf, const float4* va, const float4* vb) {
        uint32_t* Ah = sm + buf*4*BPL;
        uint32_t* Al = Ah + BPL;
        uint32_t* Bh = Ah + 2*BPL;
        uint32_t* Bl = Ah + 3*BPL;
        int kp = cG >> 1;
        #pragma unroll
        for (int q = 0; q < 4; q++) {
            int r = rA + 32*q;
            uint32_t h, l;
            split2(va[q].x, va[q].y, h, l); Ah[r*BS32+kp]   = h; Al[r*BS32+kp]   = l;
            split2(va[q].z, va[q].w, h, l); Ah[r*BS32+kp+1] = h; Al[r*BS32+kp+1] = l;
            split2(vb[q].x, vb[q].y, h, l); Bh[r*BS32+kp]   = h; Bl[r*BS32+kp]   = l;
            split2(vb[q].z, vb[q].w, h, l); Bh[r*BS32+kp+1] = h; Bl[r*BS32+kp+1] = l;
        }
    };

    {
        float4 va[4], vb[4];
        ldtile(0, va, vb);
        sttile(0, va, vb);
    }
    __syncthreads();
    for (int s = 0; s < nst; s++) {
        float4 va[4], vb[4];
        if (s + 1 < nst) ldtile(s + 1, va, vb);
        const uint32_t* base = sm + (s & 1) * 4 * BPL;
        {
            const uint32_t* Ah = base; const uint32_t* Al = base + BPL;
            const uint32_t* Bh = base + 2*BPL; const uint32_t* Bl = base + 3*BPL;
            int lr = lane >> 2, lc = lane & 3;
            for (int kk = 0; kk < 2; kk++) {
                int kp = kk*8 + lc;
                uint32_t ah[2][4], al[2][4];
                #pragma unroll
                for (int mi = 0; mi < 2; mi++) {
                    int r = warpRow + 16*mi + lr;
                    ah[mi][0] = Ah[r*BS32+kp];     ah[mi][1] = Ah[(r+8)*BS32+kp];
                    ah[mi][2] = Ah[r*BS32+kp+4];   ah[mi][3] = Ah[(r+8)*BS32+kp+4];
                    al[mi][0] = Al[r*BS32+kp];     al[mi][1] = Al[(r+8)*BS32+kp];
                    al[mi][2] = Al[r*BS32+kp+4];   al[mi][3] = Al[(r+8)*BS32+kp+4];
                }
                #pragma unroll
                for (int j = 0; j < 8; j++) {
                    int nr = warpCol + 8*j + lr;
                    uint32_t bh[2] = {Bh[nr*BS32+kp], Bh[nr*BS32+kp+4]};
                    uint32_t bl[2] = {Bl[nr*BS32+kp], Bl[nr*BS32+kp+4]};
                    mma16816(acc[0][j], ah[0], bh);
                    mma16816(acc[1][j], ah[1], bh);
                    mma16816(acc[0][j], ah[0], bl);
                    mma16816(acc[1][j], ah[1], bl);
                    mma16816(acc[0][j], al[0], bh);
                    mma16816(acc[1][j], al[1], bh);
                }
            }
        }
        if (s + 1 < nst) sttile((s + 1) & 1, va, vb);
        __syncthreads();
    }

    int lr = lane >> 2, lc = lane & 3;
    #pragma unroll
    for (int mi = 0; mi < 2; mi++) {
        int row0 = bm + warpRow + 16*mi + lr;
        #pragma unroll
        for (int j = 0; j < 8; j++) {
            int col = bn + warpCol + 8*j + 2*lc;
            if (col >= N) continue;
            float b0 = bias[col], b1 = bias[col+1];
            float v0 = fmaxf(acc[mi][j][0] + b0, 0.f), v1 = fmaxf(acc[mi][j][1] + b1, 0.f);
            float v2 = fmaxf(acc[mi][j][2] + b0, 0.f), v3 = fmaxf(acc[mi][j][3] + b1, 0.f);
            C[(size_t)row0*N + col]     = v0;
            C[(size_t)row0*N + col + 1] = v1;
            C[(size_t)(row0+8)*N + col]     = v2;
            C[(size_t)(row0+8)*N + col + 1] = v3;
        }
    }
}

// ---------------- misc kernels ----------------
__global__ void k_copy(float* __restrict__ dst, const float* __restrict__ src, size_t n) {
    size_t i = (size_t)blockIdx.x * blockDim.x + threadIdx.x;
    if (i < n) dst[i] = src[i];
}

// two-phase channel stats for LD=R (Z2)
__global__ void k_chanpart(const float* __restrict__ src, double* __restrict__ ps) {
    int ch = blockIdx.x, slab = blockIdx.y, tid = threadIdx.x;
    int nPer = NB / SLABS;
    int n0 = slab * nPer;
    double s = 0.0, q = 0.0;
    for (int e = tid; e < nPer * R; e += 256) {
        int n = n0 + e / R, l = e - (e / R) * R;
        double v = (double)src[(size_t)n*RR + (size_t)ch*R + l];
        s += v; q += v*v;
    }
    __shared__ double shs[256], shq[256];
    shs[tid] = s; shq[tid] = q;
    __syncthreads();
    for (int o = 128; o > 0; o >>= 1) {
        if (tid < o) { shs[tid] += shs[tid+o]; shq[tid] += shq[tid+o]; }
        __syncthreads();
    }
    if (tid == 0) {
        ps[(ch*SLABS + slab)*2]     = shs[0];
        ps[(ch*SLABS + slab)*2 + 1] = shq[0];
    }
}

__global__ void k_chanfin(const double* __restrict__ ps,
                          float* __restrict__ mean, float* __restrict__ rstd) {
    int ch = threadIdx.x;
    if (ch < R) {
        double s = 0.0, q = 0.0;
        #pragma unroll
        for (int k = 0; k < SLABS; k++) {
            s += ps[(ch*SLABS + k)*2];
            q += ps[(ch*SLABS + k)*2 + 1];
        }
        double tot = (double)NB * R;
        double m = s / tot;
        double var = q / tot - m*m;
        mean[ch] = (float)m;
        rstd[ch] = rsqrtf((float)var + EPSBN);
    }
}

__global__ void k_chanstats(const float* __restrict__ src, int LD,
                            float* __restrict__ mean, float* __restrict__ rstd) {
    int i = blockIdx.x, tid = threadIdx.x;
    int tot = NB * LD;
    double s = 0.0, q = 0.0;
    for (int e = tid; e < tot; e += blockDim.x) {
        int n = e / LD, l = e % LD;
        double v = (double)src[(size_t)n*(R*LD) + (size_t)i*LD + l];
        s += v; q += v*v;
    }
    __shared__ double shs[256], shq[256];
    shs[tid] = s; shq[tid] = q;
    __syncthreads();
    for (int o = blockDim.x >> 1; o > 0; o >>= 1) {
        if (tid < o) { shs[tid] += shs[tid+o]; shq[tid] += shq[tid+o]; }
        __syncthreads();
    }
    if (tid == 0) {
        double m = shs[0] / tot;
        double var = shq[0] / tot - m*m;
        mean[i] = (float)m;
        rstd[i] = rsqrtf((float)var + EPSBN);
    }
}

// BN+residual for Z operating directly on bf16 hi/lo planes (fp32 Z eliminated)
__global__ void k_updateZ(uint32_t* __restrict__ zh, uint32_t* __restrict__ zl,
                          const float* __restrict__ src,
                          const float* __restrict__ mean, const float* __restrict__ rstd,
                          const float* __restrict__ gg, const float* __restrict__ bb) {
    size_t idx2 = (size_t)blockIdx.x * blockDim.x + threadIdx.x;
    if (idx2 >= (size_t)NB*NPAIR) return;
    int p = (int)(idx2 % NPAIR);
    int i = p / 58;
    float2 s2 = ((const float2*)src)[idx2];
    uint32_t h = zh[idx2], l = zl[idx2];
    __nv_bfloat162 hb = *reinterpret_cast<__nv_bfloat162*>(&h);
    __nv_bfloat162 lb = *reinterpret_cast<__nv_bfloat162*>(&l);
    float z0 = __low2float(hb) + __low2float(lb);
    float z1 = __high2float(hb) + __high2float(lb);
    float m = mean[i], rs = rstd[i], ga = gg[i], be = bb[i];
    z0 += fmaxf((s2.x - m)*rs*ga + be, 0.f);
    z1 += fmaxf((s2.y - m)*rs*ga + be, 0.f);
    split2(z0, z1, h, l);
    zh[idx2] = h; zl[idx2] = l;
}

__global__ void k_update(float* __restrict__ buf, const float* __restrict__ src, int LD,
                         const float* __restrict__ mean, const float* __restrict__ rstd,
                         const float* __restrict__ g, const float* __restrict__ b) {
    size_t idx = (size_t)blockIdx.x * blockDim.x + threadIdx.x;
    size_t tot = (size_t)NB * R * LD;
    if (idx < tot) {
        int i = (int)((idx / LD) % R);
        float v = (src[idx] - mean[i]) * rstd[i] * g[i] + b[i];
        buf[idx] += fmaxf(v, 0.f);
    }
}

__global__ void __launch_bounds__(256)
k_gemm(const float* __restrict__ A, const float* __restrict__ W,
       const float* __restrict__ bias, float* __restrict__ Cm,
       int M, int Nc, int K) {
    __shared__ float sA[16][68];
    __shared__ float sB[16][68];
    int tid = threadIdx.x;
    int tx = tid & 15, ty = tid >> 4;
    int bm = blockIdx.y * 64, bn = blockIdx.x * 64;
    float acc[4][4];
    #pragma unroll
    for (int i = 0; i < 4; i++)
        #pragma unroll
        for (int j = 0; j < 4; j++) acc[i][j] = 0.f;

    for (int k0 = 0; k0 < K; k0 += 16) {
        #pragma unroll
        for (int q = 0; q < 4; q++) {
            int e = tid + 256*q;
            int r = e >> 4, c = e & 15;
            int gc = k0 + c;
            float av = 0.f, wv = 0.f;
            if (gc < K) {
                av = A[(size_t)(bm + r) * K + gc];
                wv = W[(size_t)(bn + r) * K + gc];
            }
            sA[c][r] = av;
            sB[c][r] = wv;
        }
        __syncthreads();
        #pragma unroll
        for (int kk = 0; kk < 16; kk++) {
            float4 a4 = *(const float4*)&sA[kk][ty*4];
            float4 b4 = *(const float4*)&sB[kk][tx*4];
            float a[4] = {a4.x, a4.y, a4.z, a4.w};
            float b[4] = {b4.x, b4.y, b4.z, b4.w};
            #pragma unroll
            for (int i = 0; i < 4; i++)
                #pragma unroll
                for (int j = 0; j < 4; j++) acc[i][j] += a[i]*b[j];
        }
        __syncthreads();
    }
    #pragma unroll
    for (int i = 0; i < 4; i++) {
        int row = bm + ty*4 + i;
        #pragma unroll
        for (int j = 0; j < 4; j++) {
            int col = bn + tx*4 + j;
            float v = acc[i][j] + bias[col];
            v = fmaxf(v, 0.f);
            Cm[(size_t)row * Nc + col] = v;
        }
    }
}

__global__ void k_colstats(const float* __restrict__ Y, int C,
                           float* __restrict__ mean, float* __restrict__ rstd) {
    int c = blockIdx.x, tid = threadIdx.x;
    double s = 0.0, q = 0.0;
    for (int r = tid; r < NB; r += blockDim.x) {
        double v = (double)Y[(size_t)r*C + c];
        s += v; q += v*v;
    }
    __shared__ double shs[256], shq[256];
    shs[tid] = s; shq[tid] = q;
    __syncthreads();
    for (int o = blockDim.x >> 1; o > 0; o >>= 1) {
        if (tid < o) { shs[tid] += shs[tid+o]; shq[tid] += shq[tid+o]; }
        __syncthreads();
    }
    if (tid == 0) {
        double m = shs[0] / NB;
        double var = shq[0] / NB - m*m;
        mean[c] = (float)m;
        rstd[c] = rsqrtf((float)var + EPSBN);
    }
}

__global__ void k_bnapply(const float* __restrict__ Y, int C, int off,
                          const float* __restrict__ mean, const float* __restrict__ rstd,
                          const float* __restrict__ g, const float* __restrict__ b,
                          float* __restrict__ XZ) {
    int idx = blockIdx.x * blockDim.x + threadIdx.x;
    if (idx < NB * C) {
        int r = idx / C, c = idx % C;
        XZ[(size_t)r*CC + off + c] = (Y[idx] - mean[c]) * rstd[c] * g[c] + b[c];
    }
}

__global__ void k_redz(const float* __restrict__ parts, const float* __restrict__ bias,
                       float* __restrict__ out) {
    int idx = blockIdx.x * blockDim.x + threadIdx.x;
    if (idx < NB * H3) {
        int c = idx % H3;
        float s = bias[c];
        #pragma unroll
        for (int k = 0; k < SPLITS; k++) s += parts[(size_t)k*NB*H3 + idx];
        out[idx] = fmaxf(s, 0.f);
    }
}

__global__ void k_c2(const float* __restrict__ hbuf, const float* __restrict__ w,
                     const float* __restrict__ b, float* __restrict__ out) {
    int gw = (blockIdx.x * blockDim.x + threadIdx.x) >> 5;
    int lane = threadIdx.x & 31;
    if (gw >= NB) return;
    const float* hrow = hbuf + (size_t)gw * C1;
    float s0 = 0.f, s1 = 0.f;
    for (int k = lane; k < C1; k += 32) {
        float hv = hrow[k];
        s0 += hv * w[k];
        s1 += hv * w[C1 + k];
    }
    #pragma unroll
    for (int o = 16; o; o >>= 1) {
        s0 += __shfl_xor_sync(0xffffffffu, s0, o);
        s1 += __shfl_xor_sync(0xffffffffu, s1, o);
    }
    if (lane == 0) { out[gw*2 + 0] = s0 + b[0]; out[gw*2 + 1] = s1 + b[1]; }
}

// ---------------- host ----------------
extern "C" void kernel_launch(void* const* d_in, const int* in_sizes, int n_in,
                              void* d_out, int out_size) {
    const float* Xin     = (const float*)d_in[0];
    const float* Zin     = (const float*)d_in[1];
    const float* conv1_w = (const float*)d_in[2];
    const float* conv1_b = (const float*)d_in[3];
    const float* conv2_w = (const float*)d_in[4];
    const float* conv2_b = (const float*)d_in[5];
    const float* node_w  = (const float*)d_in[6];
    const float* edge_w  = (const float*)d_in[7];
    const float* bn_n_g  = (const float*)d_in[8];
    const float* bn_n_b  = (const float*)d_in[9];
    const float* bn_e_g  = (const float*)d_in[10];
    const float* bn_e_b  = (const float*)d_in[11];
    const float* ln_w    = (const float*)d_in[12];
    const float* ln_b    = (const float*)d_in[13];
    const float* ln_bn_g = (const float*)d_in[14];
    const float* ln_bn_b = (const float*)d_in[15];
    const float* le_w    = (const float*)d_in[16];
    const float* le_b    = (const float*)d_in[17];
    const float* le_bn_g = (const float*)d_in[18];
    const float* le_bn_b = (const float*)d_in[19];
    const float* c1_w    = (const float*)d_in[20];
    const float* c1_b    = (const float*)d_in[21];
    const float* c2_w    = (const float*)d_in[22];
    const float* c2_b    = (const float*)d_in[23];
    float* outp = (float*)d_out;

    float *pX, *pZ2, *pX1, *pYx, *pYz, *pYzS, *pXZ, *pH;
    float *pM1, *pR1, *pMz, *pRz, *pMx, *pRx;
    double* pPS;
    uint32_t *pZh, *pZl, *pLWh, *pLWl, *pW2h, *pW2l, *pEwTh, *pEwTl;
    cudaGetSymbolAddress((void**)&pX,   g_X);
    cudaGetSymbolAddress((void**)&pZ2,  g_Z2);
    cudaGetSymbolAddress((void**)&pX1,  g_X1);
    cudaGetSymbolAddress((void**)&pYx,  g_Yx);
    cudaGetSymbolAddress((void**)&pYz,  g_Yz);
    cudaGetSymbolAddress((void**)&pYzS, g_YzS);
    cudaGetSymbolAddress((void**)&pXZ,  g_XZ);
    cudaGetSymbolAddress((void**)&pH,   g_Hb);
    cudaGetSymbolAddress((void**)&pZh,  g_Zh);
    cudaGetSymbolAddress((void**)&pZl,  g_Zl);
    cudaGetSymbolAddress((void**)&pLWh, g_LWh);
    cudaGetSymbolAddress((void**)&pLWl, g_LWl);
    cudaGetSymbolAddress((void**)&pW2h, g_W2h);
    cudaGetSymbolAddress((void**)&pW2l, g_W2l);
    cudaGetSymbolAddress((void**)&pEwTh, g_EwTh);
    cudaGetSymbolAddress((void**)&pEwTl, g_EwTl);
    cudaGetSymbolAddress((void**)&pPS,  g_ps);
    cudaGetSymbolAddress((void**)&pM1,  g_m1);
    cudaGetSymbolAddress((void**)&pR1,  g_r1);
    cudaGetSymbolAddress((void**)&pMz,  g_mz);
    cudaGetSymbolAddress((void**)&pRz,  g_rz);
    cudaGetSymbolAddress((void**)&pMx,  g_mx);
    cudaGetSymbolAddress((void**)&pRx,  g_rx);

    cudaFuncSetAttribute(k_chain, cudaFuncAttributeMaxDynamicSharedMemorySize, CH_SMEM);
    cudaFuncSetAttribute(k_tc_pre, cudaFuncAttributeMaxDynamicSharedMemorySize, BIG_SMEM);
    cudaFuncSetAttribute(k_tc_big, cudaFuncAttributeMaxDynamicSharedMemorySize, BIG_SMEM);

    auto chain = [&](int i) {
        k_prep<<<(NPAIR + 255)/256, 256>>>(conv2_w + (size_t)i*RR, edge_w + (size_t)i*RR,
                                           pW2h, pW2l, pEwTh, pEwTl);
        k_chain<<<NB, CHT, CH_SMEM>>>(pZh, pZl, pX,
                                      conv1_w + i*9, conv1_b + i*3,
                                      pW2h, pW2l, conv2_b + i*R,
                                      node_w + i*9, pEwTh, pEwTl, pZ2, pX1);
    };
    auto headZgemm = [&](int i) {
        k_tc_pre<<<dim3(H3/128, NB/128, SPLITS), 256, BIG_SMEM>>>(
            pZh, pZl, pLWh + (size_t)i*H3*NPAIR, pLWl + (size_t)i*H3*NPAIR,
            pYzS, NB, H3, NPAIR, KCHUNK2);
    };
    auto headZpost = [&](int i) {
        k_redz<<<(NB*H3 + 255)/256, 256>>>(pYzS, le_b + i*H3, pYz);
        k_colstats<<<H3, 256>>>(pYz, H3, pM1, pR1);
        k_bnapply<<<(NB*H3 + 255)/256, 256>>>(pYz, H3, 5*H + i*H3, pM1, pR1, le_bn_g + i*H3, le_bn_b + i*H3, pXZ);
    };
    auto headX = [&](int i) {
        k_gemm<<<dim3(H/64, NB/64), 256>>>(pX, ln_w + (size_t)i*H*NF, ln_b + i*H, pYx, NB, H, NF);
        k_colstats<<<H, 256>>>(pYx, H, pM1, pR1);
        k_bnapply<<<(NB*H + 255)/256, 256>>>(pYx, H, i*H, pM1, pR1, ln_bn_g + i*H, ln_bn_b + i*H, pXZ);
    };

    // startup ordered so launch index 3 (0-based) = k_chain (ncu capture slot)
    k_copy<<<(NB*NF + 255)/256, 256>>>(pX, Xin, (size_t)NB*NF);                                    // 0
    k_split<<<(int)(((size_t)NB*NPAIR + 255)/256), 256>>>(Zin, pZh, pZl, (size_t)NB*NPAIR);        // 1
    chain(0);                                                                                      // 2: k_prep, 3: k_chain <- profiled
    k_split<<<(int)(((size_t)5*H3*NPAIR + 255)/256), 256>>>(le_w, pLWh, pLWl, (size_t)5*H3*NPAIR);
    headZgemm(0);
    headZpost(0);
    headX(0);

    for (int i = 0; i < 4; i++) {
        if (i > 0) chain(i);
        // edge BN stats (two-phase), residual on planes, then Z head
        k_chanpart<<<dim3(R, SLABS), 256>>>(pZ2, pPS);
        k_chanfin<<<1, 128>>>(pPS, pMz, pRz);
        k_updateZ<<<(int)(((size_t)NB*NPAIR + 255)/256), 256>>>(pZh, pZl, pZ2, pMz, pRz,
                                                                bn_e_g + i*R, bn_e_b + i*R);
        headZgemm(i + 1);
        headZpost(i + 1);
        // node BN + residual, then X head
        k_chanstats<<<R, 256>>>(pX1, 3, pMx, pRx);
        k_update<<<(NB*NF + 255)/256, 256>>>(pX, pX1, 3, pMx, pRx, bn_n_g + i*R, bn_n_b + i*R);
        headX(i + 1);
    }

    k_tc_big<<<dim3(C1/128, NB/128, 1), 256, BIG_SMEM>>>(pXZ, c1_w, c1_b, pH, NB, C1, CC);
    k_c2<<<NB*32/256, 256>>>(pH, c2_w, c2_b, outp);
}

// round 16
// speedup vs baseline: 1.0633x; 1.0310x over previous
#include <cuda_runtime.h>
#include <cuda_bf16.h>
#include <cstdint>
#include <math.h>

#define NB 2048
#define R 116
#define RR 13456
#define NPAIR 6728
#define NF 348
#define H 128
#define H3 384
#define CC 2560
#define C1 1024
#define EPSBN 1e-5f
#define SPLITS 6
#define KCHUNK2 1136
#define CHT 1024
#define SLABS 8

// big tc kernels: stage K=32 (16 u32), row stride 20 u32
#define BS32 20
#define BPL (128*BS32)
#define BIG_SMEM (2*4*BPL*4)
// fused chain kernel: K=128 padded, row stride 68 u32
#define CS32 68
#define CPL (128*CS32)
#define CH_SMEM (6*CPL*4)

// ---------------- scratch ----------------
static __device__ float g_X [(size_t)NB*NF];
static __device__ float g_Z2[(size_t)NB*RR];
static __device__ float g_X1[(size_t)NB*NF];
static __device__ float g_Yx[(size_t)NB*H];
static __device__ float g_Yz[(size_t)NB*H3];
static __device__ float g_YzS[(size_t)SPLITS*NB*H3];
static __device__ float g_XZ[(size_t)NB*CC];
static __device__ float g_Hb[(size_t)NB*C1];
static __device__ uint32_t g_Zh[(size_t)NB*NPAIR];
static __device__ uint32_t g_Zl[(size_t)NB*NPAIR];
static __device__ uint32_t g_LWh[(size_t)5*H3*NPAIR];
static __device__ uint32_t g_LWl[(size_t)5*H3*NPAIR];
static __device__ uint32_t g_W2h[NPAIR], g_W2l[NPAIR];
static __device__ uint32_t g_EwTh[NPAIR], g_EwTl[NPAIR];
static __device__ double g_ps[R*SLABS*2];
static __device__ float g_m1[H3], g_r1[H3];
static __device__ float g_mz[R], g_rz[R], g_mx[R], g_rx[R];

// ---------------- helpers ----------------
__device__ __forceinline__ void mma16816(float* c, const uint32_t* a, const uint32_t* b) {
    asm volatile(
        "mma.sync.aligned.m16n8k16.row.col.f32.bf16.bf16.f32 "
        "{%0,%1,%2,%3}, {%4,%5,%6,%7}, {%8,%9}, {%0,%1,%2,%3};\n"
        : "+f"(c[0]), "+f"(c[1]), "+f"(c[2]), "+f"(c[3])
        : "r"(a[0]), "r"(a[1]), "r"(a[2]), "r"(a[3]), "r"(b[0]), "r"(b[1]));
}

__device__ __forceinline__ void ldsm4(uint32_t& r0, uint32_t& r1, uint32_t& r2, uint32_t& r3, uint32_t a) {
    asm volatile("ldmatrix.sync.aligned.m8n8.x4.shared.b16 {%0,%1,%2,%3}, [%4];"
        : "=r"(r0), "=r"(r1), "=r"(r2), "=r"(r3) : "r"(a));
}

__device__ __forceinline__ void ldsm4t(uint32_t& r0, uint32_t& r1, uint32_t& r2, uint32_t& r3, uint32_t a) {
    asm volatile("ldmatrix.sync.aligned.m8n8.x4.trans.shared.b16 {%0,%1,%2,%3}, [%4];"
        : "=r"(r0), "=r"(r1), "=r"(r2), "=r"(r3) : "r"(a));
}

__device__ __forceinline__ uint32_t smem_u32(const void* p) {
    uint32_t a;
    asm("{ .reg .u64 t; cvta.to.shared.u64 t, %1; cvt.u32.u64 %0, t; }" : "=r"(a) : "l"(p));
    return a;
}

__device__ __forceinline__ void split2(float x0, float x1, uint32_t& hi, uint32_t& lo) {
    __nv_bfloat16 h0 = __float2bfloat16(x0), h1 = __float2bfloat16(x1);
    float r0 = x0 - __bfloat162float(h0), r1 = x1 - __bfloat162float(h1);
    __nv_bfloat16 l0 = __float2bfloat16(r0), l1 = __float2bfloat16(r1);
    hi = (uint32_t)__bfloat16_as_ushort(h0) | ((uint32_t)__bfloat16_as_ushort(h1) << 16);
    lo = (uint32_t)__bfloat16_as_ushort(l0) | ((uint32_t)__bfloat16_as_ushort(l1) << 16);
}

// ---------------- split kernels ----------------
__global__ void k_split(const float* __restrict__ src, uint32_t* __restrict__ dh,
                        uint32_t* __restrict__ dl, size_t npairs) {
    size_t i = (size_t)blockIdx.x * blockDim.x + threadIdx.x;
    if (i < npairs) {
        float2 v = ((const float2*)src)[i];
        uint32_t h, l; split2(v.x, v.y, h, l);
        dh[i] = h; dl[i] = l;
    }
}

__global__ void k_prep(const float* __restrict__ w2, const float* __restrict__ ew,
                       uint32_t* __restrict__ w2h, uint32_t* __restrict__ w2l,
                       uint32_t* __restrict__ ewth, uint32_t* __restrict__ ewtl) {
    int i = blockIdx.x * blockDim.x + threadIdx.x;
    if (i < NPAIR) {
        float2 v = ((const float2*)w2)[i];
        uint32_t h, l; split2(v.x, v.y, h, l);
        w2h[i] = h; w2l[i] = l;
        int lrow = i / 58, k2 = i - lrow*58;
        float a0 = ew[(2*k2)*R + lrow], a1 = ew[(2*k2+1)*R + lrow];
        split2(a0, a1, h, l);
        ewth[i] = h; ewtl[i] = l;
    }
}

// ======================= fused per-sample chain kernel (1024 thr) =======================
__device__ __forceinline__ void copyplane(uint32_t* dsth, uint32_t* dstl,
                                          const uint32_t* __restrict__ sh,
                                          const uint32_t* __restrict__ sl) {
    for (int e = threadIdx.x; e < NPAIR; e += CHT) {
        int r = e / 58, c = e - r*58;
        int o = r*CS32 + c;
        dsth[o] = sh[e]; dstl[o] = sl[e];
    }
}

// ldmatrix-based bf16x3 128x128x128 block mma (32 warps, warp tile 16x32)
__device__ __forceinline__ void tc4(uint32_t aAh, uint32_t aAl, uint32_t aBh, uint32_t aBl,
                                    int wr, int wc, int lane, float acc[4][4]) {
    int lrow = lane & 15, lh = lane >> 4;
    #pragma unroll
    for (int kk = 0; kk < 8; kk++) {
        uint32_t kbyt = (uint32_t)(kk * 8) * 4;
        uint32_t ah[4], al[4];
        {
            uint32_t off = (uint32_t)((wr + lrow)*CS32 + lh*4)*4 + kbyt;
            ldsm4(ah[0], ah[1], ah[2], ah[3], aAh + off);
            ldsm4(al[0], al[1], al[2], al[3], aAl + off);
        }
        #pragma unroll
        for (int jb = 0; jb < 2; jb++) {
            uint32_t off = (uint32_t)((wc + 16*jb + lrow)*CS32 + lh*4)*4 + kbyt;
            uint32_t h0,h1,h2,h3, l0,l1,l2,l3;
            ldsm4(h0, h1, h2, h3, aBh + off);
            ldsm4(l0, l1, l2, l3, aBl + off);
            uint32_t bh0[2] = {h0, h2}, bh1[2] = {h1, h3};
            uint32_t bl0[2] = {l0, l2}, bl1[2] = {l1, l3};
            int j0 = 2*jb, j1 = 2*jb + 1;
            mma16816(acc[j0], ah, bh0); mma16816(acc[j1], ah, bh1);
            mma16816(acc[j0], ah, bl0); mma16816(acc[j1], ah, bl1);
            mma16816(acc[j0], al, bh0); mma16816(acc[j1], al, bh1);
        }
    }
}

// variant: B read transposed directly from its natural [row][col] layout via ldmatrix.trans
// computes C = A @ B  (instead of A @ B^T): B fragment (k=src row j, n=src col)
__device__ __forceinline__ void tc4t(uint32_t aAh, uint32_t aAl, uint32_t aBh, uint32_t aBl,
                                     int wr, int wc, int lane, float acc[4][4]) {
    int lrow = lane & 15, lh = lane >> 4;
    #pragma unroll
    for (int kk = 0; kk < 8; kk++) {
        uint32_t kbyt = (uint32_t)(kk * 8) * 4;
        uint32_t ah[4], al[4];
        {
            uint32_t off = (uint32_t)((wr + lrow)*CS32 + lh*4)*4 + kbyt;
            ldsm4(ah[0], ah[1], ah[2], ah[3], aAh + off);
            ldsm4(al[0], al[1], al[2], al[3], aAl + off);
        }
        #pragma unroll
        for (int jb = 0; jb < 2; jb++) {
            // source rows j = kk*16 + lrow, cols (halves) = wc + 16*jb + lh*8
            uint32_t off = (uint32_t)((kk*16 + lrow)*CS32 + (wc + 16*jb)/2 + lh*4)*4;
            uint32_t t0,t1,t2,t3, s0,s1,s2,s3;
            ldsm4t(t0, t1, t2, t3, aBh + off);
            ldsm4t(s0, s1, s2, s3, aBl + off);
            uint32_t bh0[2] = {t0, t1}, bh1[2] = {t2, t3};
            uint32_t bl0[2] = {s0, s1}, bl1[2] = {s2, s3};
            int j0 = 2*jb, j1 = 2*jb + 1;
            mma16816(acc[j0], ah, bh0); mma16816(acc[j1], ah, bh1);
            mma16816(acc[j0], ah, bl0); mma16816(acc[j1], ah, bl1);
            mma16816(acc[j0], al, bh0); mma16816(acc[j1], al, bh1);
        }
    }
}

__device__ __forceinline__ void zacc(float acc[4][4]) {
    #pragma unroll
    for (int j = 0; j < 4; j++)
        #pragma unroll
        for (int q = 0; q < 4; q++) acc[j][q] = 0.f;
}

__device__ __forceinline__ void wtile(const float acc[4][4], uint32_t* Ph, uint32_t* Pl,
                                      const float* __restrict__ bv, int wr, int wc, int lane) {
    int lr = lane >> 2, lc = lane & 3;
    int r0 = wr + lr;
    #pragma unroll
    for (int j = 0; j < 4; j++) {
        int col = wc + 8*j + 2*lc;
        bool cok = col < R;
        float b0 = 0.f, b1v = 0.f;
        if (bv && cok) { b0 = bv[col]; b1v = bv[col+1]; }
        float v0 = (cok && r0   < R) ? acc[j][0] + b0  : 0.f;
        float v1 = (cok && r0   < R) ? acc[j][1] + b1v : 0.f;
        float v2 = (cok && r0+8 < R) ? acc[j][2] + b0  : 0.f;
        float v3 = (cok && r0+8 < R) ? acc[j][3] + b1v : 0.f;
        uint32_t h, l;
        split2(v0, v1, h, l); Ph[r0*CS32 + (col>>1)] = h; Pl[r0*CS32 + (col>>1)] = l;
        split2(v2, v3, h, l); Ph[(r0+8)*CS32 + (col>>1)] = h; Pl[(r0+8)*CS32 + (col>>1)] = l;
    }
}

__global__ void __launch_bounds__(CHT, 1)
k_chain(const uint32_t* __restrict__ Zh_g, const uint32_t* __restrict__ Zl_g,
        const float* __restrict__ Xg,
        const float* __restrict__ w1, const float* __restrict__ b1,
        const uint32_t* __restrict__ W2h, const uint32_t* __restrict__ W2l,
        const float* __restrict__ b2, const float* __restrict__ nw,
        const uint32_t* __restrict__ EwTh, const uint32_t* __restrict__ EwTl,
        float* __restrict__ Z2g, float* __restrict__ X1g) {
    extern __shared__ uint32_t sm[];
    uint32_t* sZh = sm;          uint32_t* sZl = sm + CPL;
    uint32_t* sBh = sm + 2*CPL;  uint32_t* sBl = sm + 3*CPL;
    uint32_t* sCh = sm + 4*CPL;  uint32_t* sCl = sm + 5*CPL;
    float* Sf = (float*)(sm + 4*CPL);
    __shared__ float sX[NF], sk[3*R], sA1[NF];

    int tid = threadIdx.x, lane = tid & 31, w = tid >> 5;
    int wr = (w & 7) * 16, wc = (w >> 3) * 32;
    size_t n = blockIdx.x;

    uint32_t uS = smem_u32(sm);
    uint32_t uZh = uS,            uZl = uS + CPL*4;
    uint32_t uBh = uS + 2*CPL*4,  uBl = uS + 3*CPL*4;
    uint32_t uCh = uS + 4*CPL*4,  uCl = uS + 5*CPL*4;

    for (int i = tid; i < 1464; i += CHT) {
        int r, wcd;
        if (i < 696) { r = i / 6; wcd = 58 + (i - r*6); }
        else { int j = i - 696; r = 116 + (j >> 6); wcd = j & 63; }
        int o = r*CS32 + wcd;
        sZh[o] = 0; sZl[o] = 0; sBh[o] = 0; sBl[o] = 0;
    }
    copyplane(sZh, sZl, Zh_g + n*NPAIR, Zl_g + n*NPAIR);
    copyplane(sBh, sBl, W2h, W2l);
    for (int e = tid; e < NF; e += CHT) sX[e] = Xg[n*(size_t)NF + e];
    __syncthreads();

    for (int e = tid; e < 3*R; e += CHT) {
        int c = e / R, l = e - c*R;
        sk[c*R + l] = b1[c] + w1[c*3]*sX[l*3] + w1[c*3+1]*sX[l*3+1] + w1[c*3+2]*sX[l*3+2];
    }
    __syncthreads();
    for (int e = tid; e < RR; e += CHT) {
        int l = e / R, m = e - l*R;
        Sf[l*117 + m] = sk[l]*sk[m] + sk[R+l]*sk[R+m] + sk[2*R+l]*sk[2*R+m];
    }
    __syncthreads();

    // mma1: ZW = Z @ W2^T
    float acc[4][4];
    zacc(acc);
    tc4(uZh, uZl, uBh, uBl, wr, wc, lane, acc);
    __syncthreads();

    // softmax(S) -> att into sB
    for (int l = w; l < R; l += 32) {
        const float* Srow = Sf + l*117;
        bool sec = lane < 26;
        float a0 = Srow[2*lane], a1 = Srow[2*lane+1];
        float a2 = sec ? Srow[64+2*lane] : -1e30f;
        float a3 = sec ? Srow[65+2*lane] : -1e30f;
        float mx = fmaxf(fmaxf(a0, a1), fmaxf(a2, a3));
        #pragma unroll
        for (int o = 16; o; o >>= 1) mx = fmaxf(mx, __shfl_xor_sync(0xffffffffu, mx, o));
        float e0 = expf(a0-mx), e1 = expf(a1-mx);
        float e2 = sec ? expf(a2-mx) : 0.f, e3 = sec ? expf(a3-mx) : 0.f;
        float sum = e0+e1+e2+e3;
        #pragma unroll
        for (int o = 16; o; o >>= 1) sum += __shfl_xor_sync(0xffffffffu, sum, o);
        float inv = 1.f / sum;
        uint32_t h, lo;
        split2(e0*inv, e1*inv, h, lo);
        sBh[l*CS32 + lane] = h; sBl[l*CS32 + lane] = lo;
        if (sec) {
            split2(e2*inv, e3*inv, h, lo);
            sBh[l*CS32 + 32+lane] = h; sBl[l*CS32 + 32+lane] = lo;
        }
    }
    __syncthreads();

    // ZW (+conv2_b) -> sC
    wtile(acc, sCh, sCl, b2, wr, wc, lane);
    __syncthreads();

    // mma2: P = ZW @ att^T
    zacc(acc);
    tc4(uCh, uCl, uBh, uBl, wr, wc, lane, acc);
    __syncthreads();

    // P -> sC (Z stays in sZ; mma3 reads it transposed via ldmatrix.trans)
    wtile(acc, sCh, sCl, (const float*)0, wr, wc, lane);
    __syncthreads();

    // mma3: T = P @ Z  (B = Z read transposed in-place)
    float accT[4][4];
    zacc(accT);
    tc4t(uCh, uCl, uZh, uZl, wr, wc, lane, accT);

    // X1 stage1: A1 = P @ X (P in sC)
    if (tid < NF) {
        int m = tid / 3, f = tid - m*3;
        float a = 0.f;
        for (int p = 0; p < 58; p++) {
            uint32_t hw = sCh[m*CS32 + p], lw = sCl[m*CS32 + p];
            __nv_bfloat162 hb = *reinterpret_cast<__nv_bfloat162*>(&hw);
            __nv_bfloat162 lb = *reinterpret_cast<__nv_bfloat162*>(&lw);
            float p0 = __low2float(hb) + __low2float(lb);
            float p1 = __high2float(hb) + __high2float(lb);
            a += p0 * sX[(2*p)*3 + f] + p1 * sX[(2*p+1)*3 + f];
        }
        sA1[tid] = a;
    }
    __syncthreads();

    if (tid < NF) {
        int m = tid / 3, l = tid - m*3;
        X1g[n*(size_t)NF + tid] = sA1[m*3]*nw[l] + sA1[m*3+1]*nw[3+l] + sA1[m*3+2]*nw[6+l];
    }
    wtile(accT, sCh, sCl, (const float*)0, wr, wc, lane);
    copyplane(sBh, sBl, EwTh, EwTl);
    __syncthreads();

    // mma4: Z2 = T @ EwT^T
    zacc(acc);
    tc4(uCh, uCl, uBh, uBl, wr, wc, lane, acc);

    float* out = Z2g + n*(size_t)RR;
    int lr = lane >> 2, lc = lane & 3;
    int r0 = wr + lr;
    #pragma unroll
    for (int j = 0; j < 4; j++) {
        int col = wc + 8*j + 2*lc;
        if (col >= R) continue;
        if (r0 < R) {
            out[r0*R + col]   = acc[j][0];
            out[r0*R + col+1] = acc[j][1];
        }
        if (r0 + 8 < R) {
            out[(r0+8)*R + col]   = acc[j][2];
            out[(r0+8)*R + col+1] = acc[j][3];
        }
    }
}

// ---------------- pre-split big GEMM (headZ, split-K, K-stage=32): C_partial = A @ B^T ----------------
__global__ void __launch_bounds__(256)
k_tc_pre(const uint32_t* __restrict__ Ah_g, const uint32_t* __restrict__ Al_g,
         const uint32_t* __restrict__ Bh_g, const uint32_t* __restrict__ Bl_g,
         float* __restrict__ C, int M, int N, int K2, int kChunk2) {
    extern __shared__ uint32_t sm[];
    int tid = threadIdx.x, lane = tid & 31, w = tid >> 5;
    int warpRow = (w & 3) * 32, warpCol = (w >> 2) * 64;
    int bm = blockIdx.y * 128, bn = blockIdx.x * 128;
    int kb = blockIdx.z * kChunk2;
    int ke = min(kb + kChunk2, K2);
    int nst = (ke - kb + 15) / 16;

    float acc[2][8][4];
    #pragma unroll
    for (int mi = 0; mi < 2; mi++)
        #pragma unroll
        for (int j = 0; j < 8; j++)
            #pragma unroll
            for (int q = 0; q < 4; q++) acc[mi][j][q] = 0.f;

    int r0t = tid >> 2;
    int c4 = (tid & 3) * 4;

    uint4 vah[2], val_[2], vbh[2], vbl[2];
    auto ldt = [&](int s) {
        int ku = kb + s*16 + c4;
        bool ok = (ku + 4) <= ke;
        const uint4 z4 = make_uint4(0,0,0,0);
        #pragma unroll
        for (int q = 0; q < 2; q++) {
            int r = r0t + 64*q;
            size_t ao = (size_t)(bm + r) * K2 + ku;
            size_t bo = (size_t)(bn + r) * K2 + ku;
            vah[q] = ok ? *(const uint4*)(Ah_g + ao) : z4;
            val_[q] = ok ? *(const uint4*)(Al_g + ao) : z4;
            vbh[q] = ok ? *(const uint4*)(Bh_g + bo) : z4;
            vbl[q] = ok ? *(const uint4*)(Bl_g + bo) : z4;
        }
    };
    auto stt = [&](int buf) {
        uint32_t* Ah = sm + buf*4*BPL;
        uint32_t* Al = Ah + BPL;
        uint32_t* Bh = Ah + 2*BPL;
        uint32_t* Bl = Ah + 3*BPL;
        #pragma unroll
        for (int q = 0; q < 2; q++) {
            int r = r0t + 64*q;
            *(uint4*)(Ah + r*BS32 + c4) = vah[q];
            *(uint4*)(Al + r*BS32 + c4) = val_[q];
            *(uint4*)(Bh + r*BS32 + c4) = vbh[q];
            *(uint4*)(Bl + r*BS32 + c4) = vbl[q];
        }
    };

    ldt(0); stt(0);
    __syncthreads();
    for (int s = 0; s < nst; s++) {
        if (s + 1 < nst) ldt(s + 1);
        const uint32_t* base = sm + (s & 1) * 4 * BPL;
        {
            const uint32_t* Ah = base; const uint32_t* Al = base + BPL;
            const uint32_t* Bh = base + 2*BPL; const uint32_t* Bl = base + 3*BPL;
            int lr = lane >> 2, lc = lane & 3;
            for (int kk = 0; kk < 2; kk++) {
                int kp = kk*8 + lc;
                uint32_t ah[2][4], al[2][4];
                #pragma unroll
                for (int mi = 0; mi < 2; mi++) {
                    int r = warpRow + 16*mi + lr;
                    ah[mi][0] = Ah[r*BS32+kp];     ah[mi][1] = Ah[(r+8)*BS32+kp];
                    ah[mi][2] = Ah[r*BS32+kp+4];   ah[mi][3] = Ah[(r+8)*BS32+kp+4];
                    al[mi][0] = Al[r*BS32+kp];     al[mi][1] = Al[(r+8)*BS32+kp];
                    al[mi][2] = Al[r*BS32+kp+4];   al[mi][3] = Al[(r+8)*BS32+kp+4];
                }
                #pragma unroll
                for (int j = 0; j < 8; j++) {
                    int nr = warpCol + 8*j + lr;
                    uint32_t bh[2] = {Bh[nr*BS32+kp], Bh[nr*BS32+kp+4]};
                    uint32_t bl[2] = {Bl[nr*BS32+kp], Bl[nr*BS32+kp+4]};
                    mma16816(acc[0][j], ah[0], bh);
                    mma16816(acc[1][j], ah[1], bh);
                    mma16816(acc[0][j], ah[0], bl);
                    mma16816(acc[1][j], ah[1], bl);
                    mma16816(acc[0][j], al[0], bh);
                    mma16816(acc[1][j], al[1], bh);
                }
            }
        }
        if (s + 1 < nst) stt((s + 1) & 1);
        __syncthreads();
    }

    int lr = lane >> 2, lc = lane & 3;
    float* Cp = C + (size_t)blockIdx.z * M * N;
    #pragma unroll
    for (int mi = 0; mi < 2; mi++) {
        int row0 = bm + warpRow + 16*mi + lr;
        #pragma unroll
        for (int j = 0; j < 8; j++) {
            int col = bn + warpCol + 8*j + 2*lc;
            if (col >= N) continue;
            Cp[(size_t)row0*N + col]     = acc[mi][j][0];
            Cp[(size_t)row0*N + col + 1] = acc[mi][j][1];
            Cp[(size_t)(row0+8)*N + col]     = acc[mi][j][2];
            Cp[(size_t)(row0+8)*N + col + 1] = acc[mi][j][3];
        }
    }
}

// ---------------- fp32-input big GEMM (c1): C = relu(A @ B^T + bias) ----------------
__global__ void __launch_bounds__(256)
k_tc_big(const float* __restrict__ A, const float* __restrict__ B,
         const float* __restrict__ bias, float* __restrict__ C,
         int M, int N, int K) {
    extern __shared__ uint32_t sm[];
    int tid = threadIdx.x, lane = tid & 31, w = tid >> 5;
    int warpRow = (w & 3) * 32, warpCol = (w >> 2) * 64;
    int bm = blockIdx.y * 128, bn = blockIdx.x * 128;
    int nst = (K + 31) / 32;

    float acc[2][8][4];
    #pragma unroll
    for (int mi = 0; mi < 2; mi++)
        #pragma unroll
        for (int j = 0; j < 8; j++)
            #pragma unroll
            for (int q = 0; q < 4; q++) acc[mi][j][q] = 0.f;

    int rA = tid >> 3;
    int cG = (tid & 7) * 4;

    auto ldtile = [&](int s, float4* va, float4* vb) {
        int k0 = s*32 + cG;
        bool kok = (k0 + 4 <= K);
        #pragma unroll
        for (int q = 0; q < 4; q++) {
            const float* ap = A + (size_t)(bm + rA + 32*q) * K;
            va[q] = kok ? *(const float4*)(ap + k0) : make_float4(0.f,0.f,0.f,0.f);
            int br = bn + rA + 32*q;
            const float* bp = B + (size_t)br * K;
            vb[q] = (kok && br < N) ? *(const float4*)(bp + k0) : make_float4(0.f,0.f,0.f,0.f);
        }
    };
    auto sttile = [&](int buf, const float4* va, const float4* vb) {
        uint32_t* Ah = sm + buf*4*BPL;
        uint32_t* Al = Ah + BPL;
        uint32_t* Bh = Ah + 2*BPL;
        uint32_t* Bl = Ah + 3*BPL;
        int kp = cG >> 1;
        #pragma unroll
        for (int q = 0; q < 4; q++) {
            int r = rA + 32*q;
            uint32_t h, l;
            split2(va[q].x, va[q].y, h, l); Ah[r*BS32+kp]   = h; Al[r*BS32+kp]   = l;
            split2(va[q].z, va[q].w, h, l); Ah[r*BS32+kp+1] = h; Al[r*BS32+kp+1] = l;
            split2(vb[q].x, vb[q].y, h, l); Bh[r*BS32+kp]   = h; Bl[r*BS32+kp]   = l;
            split2(vb[q].z, vb[q].w, h, l); Bh[r*BS32+kp+1] = h; Bl[r*BS32+kp+1] = l;
        }
    };

    {
        float4 va[4], vb[4];
        ldtile(0, va, vb);
        sttile(0, va, vb);
    }
    __syncthreads();
    for (int s = 0; s < nst; s++) {
        float4 va[4], vb[4];
        if (s + 1 < nst) ldtile(s + 1, va, vb);
        const uint32_t* base = sm + (s & 1) * 4 * BPL;
        {
            const uint32_t* Ah = base; const uint32_t* Al = base + BPL;
            const uint32_t* Bh = base + 2*BPL; const uint32_t* Bl = base + 3*BPL;
            int lr = lane >> 2, lc = lane & 3;
            for (int kk = 0; kk < 2; kk++) {
                int kp = kk*8 + lc;
                uint32_t ah[2][4], al[2][4];
                #pragma unroll
                for (int mi = 0; mi < 2; mi++) {
                    int r = warpRow + 16*mi + lr;
                    ah[mi][0] = Ah[r*BS32+kp];     ah[mi][1] = Ah[(r+8)*BS32+kp];
                    ah[mi][2] = Ah[r*BS32+kp+4];   ah[mi][3] = Ah[(r+8)*BS32+kp+4];
                    al[mi][0] = Al[r*BS32+kp];     al[mi][1] = Al[(r+8)*BS32+kp];
                    al[mi][2] = Al[r*BS32+kp+4];   al[mi][3] = Al[(r+8)*BS32+kp+4];
                }
                #pragma unroll
                for (int j = 0; j < 8; j++) {
                    int nr = warpCol + 8*j + lr;
                    uint32_t bh[2] = {Bh[nr*BS32+kp], Bh[nr*BS32+kp+4]};
                    uint32_t bl[2] = {Bl[nr*BS32+kp], Bl[nr*BS32+kp+4]};
                    mma16816(acc[0][j], ah[0], bh);
                    mma16816(acc[1][j], ah[1], bh);
                    mma16816(acc[0][j], ah[0], bl);
                    mma16816(acc[1][j], ah[1], bl);
                    mma16816(acc[0][j], al[0], bh);
                    mma16816(acc[1][j], al[1], bh);
                }
            }
        }
        if (s + 1 < nst) sttile((s + 1) & 1, va, vb);
        __syncthreads();
    }

    int lr = lane >> 2, lc = lane & 3;
    #pragma unroll
    for (int mi = 0; mi < 2; mi++) {
        int row0 = bm + warpRow + 16*mi + lr;
        #pragma unroll
        for (int j = 0; j < 8; j++) {
            int col = bn + warpCol + 8*j + 2*lc;
            if (col >= N) continue;
            float b0 = bias[col], b1 = bias[col+1];
            float v0 = fmaxf(acc[mi][j][0] + b0, 0.f), v1 = fmaxf(acc[mi][j][1] + b1, 0.f);
            float v2 = fmaxf(acc[mi][j][2] + b0, 0.f), v3 = fmaxf(acc[mi][j][3] + b1, 0.f);
            C[(size_t)row0*N + col]     = v0;
            C[(size_t)row0*N + col + 1] = v1;
            C[(size_t)(row0+8)*N + col]     = v2;
            C[(size_t)(row0+8)*N + col + 1] = v3;
        }
    }
}

// ---------------- misc kernels ----------------
__global__ void k_copy(float* __restrict__ dst, const float* __restrict__ src, size_t n) {
    size_t i = (size_t)blockIdx.x * blockDim.x + threadIdx.x;
    if (i < n) dst[i] = src[i];
}

// two-phase channel stats for LD=R (Z2)
__global__ void k_chanpart(const float* __restrict__ src, double* __restrict__ ps) {
    int ch = blockIdx.x, slab = blockIdx.y, tid = threadIdx.x;
    int nPer = NB / SLABS;
    int n0 = slab * nPer;
    double s = 0.0, q = 0.0;
    for (int e = tid; e < nPer * R; e += 256) {
        int n = n0 + e / R, l = e - (e / R) * R;
        double v = (double)src[(size_t)n*RR + (size_t)ch*R + l];
        s += v; q += v*v;
    }
    __shared__ double shs[256], shq[256];
    shs[tid] = s; shq[tid] = q;
    __syncthreads();
    for (int o = 128; o > 0; o >>= 1) {
        if (tid < o) { shs[tid] += shs[tid+o]; shq[tid] += shq[tid+o]; }
        __syncthreads();
    }
    if (tid == 0) {
        ps[(ch*SLABS + slab)*2]     = shs[0];
        ps[(ch*SLABS + slab)*2 + 1] = shq[0];
    }
}

__global__ void k_chanfin(const double* __restrict__ ps,
                          float* __restrict__ mean, float* __restrict__ rstd) {
    int ch = threadIdx.x;
    if (ch < R) {
        double s = 0.0, q = 0.0;
        #pragma unroll
        for (int k = 0; k < SLABS; k++) {
            s += ps[(ch*SLABS + k)*2];
            q += ps[(ch*SLABS + k)*2 + 1];
        }
        double tot = (double)NB * R;
        double m = s / tot;
        double var = q / tot - m*m;
        mean[ch] = (float)m;
        rstd[ch] = rsqrtf((float)var + EPSBN);
    }
}

__global__ void k_chanstats(const float* __restrict__ src, int LD,
                            float* __restrict__ mean, float* __restrict__ rstd) {
    int i = blockIdx.x, tid = threadIdx.x;
    int tot = NB * LD;
    double s = 0.0, q = 0.0;
    for (int e = tid; e < tot; e += blockDim.x) {
        int n = e / LD, l = e % LD;
        double v = (double)src[(size_t)n*(R*LD) + (size_t)i*LD + l];
        s += v; q += v*v;
    }
    __shared__ double shs[256], shq[256];
    shs[tid] = s; shq[tid] = q;
    __syncthreads();
    for (int o = blockDim.x >> 1; o > 0; o >>= 1) {
        if (tid < o) { shs[tid] += shs[tid+o]; shq[tid] += shq[tid+o]; }
        __syncthreads();
    }
    if (tid == 0) {
        double m = shs[0] / tot;
        double var = shq[0] / tot - m*m;
        mean[i] = (float)m;
        rstd[i] = rsqrtf((float)var + EPSBN);
    }
}

// BN+residual for Z operating directly on bf16 hi/lo planes
__global__ void k_updateZ(uint32_t* __restrict__ zh, uint32_t* __restrict__ zl,
                          const float* __restrict__ src,
                          const float* __restrict__ mean, const float* __restrict__ rstd,
                          const float* __restrict__ gg, const float* __restrict__ bb) {
    size_t idx2 = (size_t)blockIdx.x * blockDim.x + threadIdx.x;
    if (idx2 >= (size_t)NB*NPAIR) return;
    int p = (int)(idx2 % NPAIR);
    int i = p / 58;
    float2 s2 = ((const float2*)src)[idx2];
    uint32_t h = zh[idx2], l = zl[idx2];
    __nv_bfloat162 hb = *reinterpret_cast<__nv_bfloat162*>(&h);
    __nv_bfloat162 lb = *reinterpret_cast<__nv_bfloat162*>(&l);
    float z0 = __low2float(hb) + __low2float(lb);
    float z1 = __high2float(hb) + __high2float(lb);
    float m = mean[i], rs = rstd[i], ga = gg[i], be = bb[i];
    z0 += fmaxf((s2.x - m)*rs*ga + be, 0.f);
    z1 += fmaxf((s2.y - m)*rs*ga + be, 0.f);
    split2(z0, z1, h, l);
    zh[idx2] = h; zl[idx2] = l;
}

__global__ void k_update(float* __restrict__ buf, const float* __restrict__ src, int LD,
                         const float* __restrict__ mean, const float* __restrict__ rstd,
                         const float* __restrict__ g, const float* __restrict__ b) {
    size_t idx = (size_t)blockIdx.x * blockDim.x + threadIdx.x;
    size_t tot = (size_t)NB * R * LD;
    if (idx < tot) {
        int i = (int)((idx / LD) % R);
        float v = (src[idx] - mean[i]) * rstd[i] * g[i] + b[i];
        buf[idx] += fmaxf(v, 0.f);
    }
}

__global__ void __launch_bounds__(256)
k_gemm(const float* __restrict__ A, const float* __restrict__ W,
       const float* __restrict__ bias, float* __restrict__ Cm,
       int M, int Nc, int K) {
    __shared__ float sA[16][68];
    __shared__ float sB[16][68];
    int tid = threadIdx.x;
    int tx = tid & 15, ty = tid >> 4;
    int bm = blockIdx.y * 64, bn = blockIdx.x * 64;
    float acc[4][4];
    #pragma unroll
    for (int i = 0; i < 4; i++)
        #pragma unroll
        for (int j = 0; j < 4; j++) acc[i][j] = 0.f;

    for (int k0 = 0; k0 < K; k0 += 16) {
        #pragma unroll
        for (int q = 0; q < 4; q++) {
            int e = tid + 256*q;
            int r = e >> 4, c = e & 15;
            int gc = k0 + c;
            float av = 0.f, wv = 0.f;
            if (gc < K) {
                av = A[(size_t)(bm + r) * K + gc];
                wv = W[(size_t)(bn + r) * K + gc];
            }
            sA[c][r] = av;
            sB[c][r] = wv;
        }
        __syncthreads();
        #pragma unroll
        for (int kk = 0; kk < 16; kk++) {
            float4 a4 = *(const float4*)&sA[kk][ty*4];
            float4 b4 = *(const float4*)&sB[kk][tx*4];
            float a[4] = {a4.x, a4.y, a4.z, a4.w};
            float b[4] = {b4.x, b4.y, b4.z, b4.w};
            #pragma unroll
            for (int i = 0; i < 4; i++)
                #pragma unroll
                for (int j = 0; j < 4; j++) acc[i][j] += a[i]*b[j];
        }
        __syncthreads();
    }
    #pragma unroll
    for (int i = 0; i < 4; i++) {
        int row = bm + ty*4 + i;
        #pragma unroll
        for (int j = 0; j < 4; j++) {
            int col = bn + tx*4 + j;
            float v = acc[i][j] + bias[col];
            v = fmaxf(v, 0.f);
            Cm[(size_t)row * Nc + col] = v;
        }
    }
}

__global__ void k_colstats(const float* __restrict__ Y, int C,
                           float* __restrict__ mean, float* __restrict__ rstd) {
    int c = blockIdx.x, tid = threadIdx.x;
    double s = 0.0, q = 0.0;
    for (int r = tid; r < NB; r += blockDim.x) {
        double v = (double)Y[(size_t)r*C + c];
        s += v; q += v*v;
    }
    __shared__ double shs[256], shq[256];
    shs[tid] = s; shq[tid] = q;
    __syncthreads();
    for (int o = blockDim.x >> 1; o > 0; o >>= 1) {
        if (tid < o) { shs[tid] += shs[tid+o]; shq[tid] += shq[tid+o]; }
        __syncthreads();
    }
    if (tid == 0) {
        double m = shs[0] / NB;
        double var = shq[0] / NB - m*m;
        mean[c] = (float)m;
        rstd[c] = rsqrtf((float)var + EPSBN);
    }
}

__global__ void k_bnapply(const float* __restrict__ Y, int C, int off,
                          const float* __restrict__ mean, const float* __restrict__ rstd,
                          const float* __restrict__ g, const float* __restrict__ b,
                          float* __restrict__ XZ) {
    int idx = blockIdx.x * blockDim.x + threadIdx.x;
    if (idx < NB * C) {
        int r = idx / C, c = idx % C;
        XZ[(size_t)r*CC + off + c] = (Y[idx] - mean[c]) * rstd[c] * g[c] + b[c];
    }
}

__global__ void k_redz(const float* __restrict__ parts, const float* __restrict__ bias,
                       float* __restrict__ out) {
    int idx = blockIdx.x * blockDim.x + threadIdx.x;
    if (idx < NB * H3) {
        int c = idx % H3;
        float s = bias[c];
        #pragma unroll
        for (int k = 0; k < SPLITS; k++) s += parts[(size_t)k*NB*H3 + idx];
        out[idx] = fmaxf(s, 0.f);
    }
}

__global__ void k_c2(const float* __restrict__ hbuf, const float* __restrict__ w,
                     const float* __restrict__ b, float* __restrict__ out) {
    int gw = (blockIdx.x * blockDim.x + threadIdx.x) >> 5;
    int lane = threadIdx.x & 31;
    if (gw >= NB) return;
    const float* hrow = hbuf + (size_t)gw * C1;
    float s0 = 0.f, s1 = 0.f;
    for (int k = lane; k < C1; k += 32) {
        float hv = hrow[k];
        s0 += hv * w[k];
        s1 += hv * w[C1 + k];
    }
    #pragma unroll
    for (int o = 16; o; o >>= 1) {
        s0 += __shfl_xor_sync(0xffffffffu, s0, o);
        s1 += __shfl_xor_sync(0xffffffffu, s1, o);
    }
    if (lane == 0) { out[gw*2 + 0] = s0 + b[0]; out[gw*2 + 1] = s1 + b[1]; }
}

// ---------------- host ----------------
extern "C" void kernel_launch(void* const* d_in, const int* in_sizes, int n_in,
                              void* d_out, int out_size) {
    const float* Xin     = (const float*)d_in[0];
    const float* Zin     = (const float*)d_in[1];
    const float* conv1_w = (const float*)d_in[2];
    const float* conv1_b = (const float*)d_in[3];
    const float* conv2_w = (const float*)d_in[4];
    const float* conv2_b = (const float*)d_in[5];
    const float* node_w  = (const float*)d_in[6];
    const float* edge_w  = (const float*)d_in[7];
    const float* bn_n_g  = (const float*)d_in[8];
    const float* bn_n_b  = (const float*)d_in[9];
    const float* bn_e_g  = (const float*)d_in[10];
    const float* bn_e_b  = (const float*)d_in[11];
    const float* ln_w    = (const float*)d_in[12];
    const float* ln_b    = (const float*)d_in[13];
    const float* ln_bn_g = (const float*)d_in[14];
    const float* ln_bn_b = (const float*)d_in[15];
    const float* le_w    = (const float*)d_in[16];
    const float* le_b    = (const float*)d_in[17];
    const float* le_bn_g = (const float*)d_in[18];
    const float* le_bn_b = (const float*)d_in[19];
    const float* c1_w    = (const float*)d_in[20];
    const float* c1_b    = (const float*)d_in[21];
    const float* c2_w    = (const float*)d_in[22];
    const float* c2_b    = (const float*)d_in[23];
    float* outp = (float*)d_out;

    float *pX, *pZ2, *pX1, *pYx, *pYz, *pYzS, *pXZ, *pH;
    float *pM1, *pR1, *pMz, *pRz, *pMx, *pRx;
    double* pPS;
    uint32_t *pZh, *pZl, *pLWh, *pLWl, *pW2h, *pW2l, *pEwTh, *pEwTl;
    cudaGetSymbolAddress((void**)&pX,   g_X);
    cudaGetSymbolAddress((void**)&pZ2,  g_Z2);
    cudaGetSymbolAddress((void**)&pX1,  g_X1);
    cudaGetSymbolAddress((void**)&pYx,  g_Yx);
    cudaGetSymbolAddress((void**)&pYz,  g_Yz);
    cudaGetSymbolAddress((void**)&pYzS, g_YzS);
    cudaGetSymbolAddress((void**)&pXZ,  g_XZ);
    cudaGetSymbolAddress((void**)&pH,   g_Hb);
    cudaGetSymbolAddress((void**)&pZh,  g_Zh);
    cudaGetSymbolAddress((void**)&pZl,  g_Zl);
    cudaGetSymbolAddress((void**)&pLWh, g_LWh);
    cudaGetSymbolAddress((void**)&pLWl, g_LWl);
    cudaGetSymbolAddress((void**)&pW2h, g_W2h);
    cudaGetSymbolAddress((void**)&pW2l, g_W2l);
    cudaGetSymbolAddress((void**)&pEwTh, g_EwTh);
    cudaGetSymbolAddress((void**)&pEwTl, g_EwTl);
    cudaGetSymbolAddress((void**)&pPS,  g_ps);
    cudaGetSymbolAddress((void**)&pM1,  g_m1);
    cudaGetSymbolAddress((void**)&pR1,  g_r1);
    cudaGetSymbolAddress((void**)&pMz,  g_mz);
    cudaGetSymbolAddress((void**)&pRz,  g_rz);
    cudaGetSymbolAddress((void**)&pMx,  g_mx);
    cudaGetSymbolAddress((void**)&pRx,  g_rx);

    cudaFuncSetAttribute(k_chain, cudaFuncAttributeMaxDynamicSharedMemorySize, CH_SMEM);
    cudaFuncSetAttribute(k_tc_pre, cudaFuncAttributeMaxDynamicSharedMemorySize, BIG_SMEM);
    cudaFuncSetAttribute(k_tc_big, cudaFuncAttributeMaxDynamicSharedMemorySize, BIG_SMEM);

    auto chain = [&](int i) {
        k_prep<<<(NPAIR + 255)/256, 256>>>(conv2_w + (size_t)i*RR, edge_w + (size_t)i*RR,
                                           pW2h, pW2l, pEwTh, pEwTl);
        k_chain<<<NB, CHT, CH_SMEM>>>(pZh, pZl, pX,
                                      conv1_w + i*9, conv1_b + i*3,
                                      pW2h, pW2l, conv2_b + i*R,
                                      node_w + i*9, pEwTh, pEwTl, pZ2, pX1);
    };
    auto headZgemm = [&](int i) {
        k_tc_pre<<<dim3(H3/128, NB/128, SPLITS), 256, BIG_SMEM>>>(
            pZh, pZl, pLWh + (size_t)i*H3*NPAIR, pLWl + (size_t)i*H3*NPAIR,
            pYzS, NB, H3, NPAIR, KCHUNK2);
    };
    auto headZpost = [&](int i) {
        k_redz<<<(NB*H3 + 255)/256, 256>>>(pYzS, le_b + i*H3, pYz);
        k_colstats<<<H3, 256>>>(pYz, H3, pM1, pR1);
        k_bnapply<<<(NB*H3 + 255)/256, 256>>>(pYz, H3, 5*H + i*H3, pM1, pR1, le_bn_g + i*H3, le_bn_b + i*H3, pXZ);
    };
    auto headX = [&](int i) {
        k_gemm<<<dim3(H/64, NB/64), 256>>>(pX, ln_w + (size_t)i*H*NF, ln_b + i*H, pYx, NB, H, NF);
        k_colstats<<<H, 256>>>(pYx, H, pM1, pR1);
        k_bnapply<<<(NB*H + 255)/256, 256>>>(pYx, H, i*H, pM1, pR1, ln_bn_g + i*H, ln_bn_b + i*H, pXZ);
    };

    // startup ordered so launch index 3 (0-based) = k_chain (ncu capture slot)
    k_copy<<<(NB*NF + 255)/256, 256>>>(pX, Xin, (size_t)NB*NF);                                    // 0
    k_split<<<(int)(((size_t)NB*NPAIR + 255)/256), 256>>>(Zin, pZh, pZl, (size_t)NB*NPAIR);        // 1
    chain(0);                                                                                      // 2: k_prep, 3: k_chain <- profiled
    k_split<<<(int)(((size_t)5*H3*NPAIR + 255)/256), 256>>>(le_w, pLWh, pLWl, (size_t)5*H3*NPAIR);
    headZgemm(0);
    headZpost(0);
    headX(0);

    for (int i = 0; i < 4; i++) {
        if (i > 0) chain(i);
        // edge BN stats (two-phase), residual on planes, then Z head
        k_chanpart<<<dim3(R, SLABS), 256>>>(pZ2, pPS);
        k_chanfin<<<1, 128>>>(pPS, pMz, pRz);
        k_updateZ<<<(int)(((size_t)NB*NPAIR + 255)/256), 256>>>(pZh, pZl, pZ2, pMz, pRz,
                                                                bn_e_g + i*R, bn_e_b + i*R);
        headZgemm(i + 1);
        headZpost(i + 1);
        // node BN + residual, then X head
        k_chanstats<<<R, 256>>>(pX1, 3, pMx, pRx);
        k_update<<<(NB*NF + 255)/256, 256>>>(pX, pX1, 3, pMx, pRx, bn_n_g + i*R, bn_n_b + i*R);
        headX(i + 1);
    }

    k_tc_big<<<dim3(C1/128, NB/128, 1), 256, BIG_SMEM>>>(pXZ, c1_w, c1_b, pH, NB, C1, CC);
    k_c2<<<NB*32/256, 256>>>(pH, c2_w, c2_b, outp);
}

// round 17
// speedup vs baseline: 1.0639x; 1.0005x over previous
#include <cuda_runtime.h>
#include <cuda_bf16.h>
#include <cstdint>
#include <math.h>

#define NB 2048
#define R 116
#define RR 13456
#define NPAIR 6728
#define NF 348
#define H 128
#define H3 384
#define CC 2560
#define C1 1024
#define EPSBN 1e-5f
#define SPLITS 6
#define KCHUNK2 1136
#define CHT 1024
#define SLABS 8

// big tc kernels: stage K=32 (16 u32), row stride 20 u32
#define BS32 20
#define BPL (128*BS32)
#define BIG_SMEM (2*4*BPL*4)
// fused chain kernel: K=128 padded, row stride 68 u32
#define CS32 68
#define CPL (128*CS32)
#define CH_SMEM (6*CPL*4)

// ---------------- scratch ----------------
static __device__ float g_X [(size_t)NB*NF];
static __device__ float g_Z2[(size_t)NB*RR];
static __device__ float g_X1[(size_t)NB*NF];
static __device__ float g_Yx[(size_t)NB*H];
static __device__ float g_Yz[(size_t)NB*H3];
static __device__ float g_YzS[(size_t)SPLITS*NB*H3];
static __device__ float g_XZ[(size_t)NB*CC];
static __device__ float g_Hb[(size_t)NB*C1];
static __device__ uint32_t g_Zh[(size_t)NB*NPAIR];
static __device__ uint32_t g_Zl[(size_t)NB*NPAIR];
static __device__ uint32_t g_LWh[(size_t)5*H3*NPAIR];
static __device__ uint32_t g_LWl[(size_t)5*H3*NPAIR];
static __device__ uint32_t g_W2h[NPAIR], g_W2l[NPAIR];
static __device__ uint32_t g_EwTh[NPAIR], g_EwTl[NPAIR];
static __device__ double g_ps[R*SLABS*2];
static __device__ float g_m1[H3], g_r1[H3];
static __device__ float g_mz[R], g_rz[R], g_mx[R], g_rx[R];

// ---------------- helpers ----------------
__device__ __forceinline__ void mma16816(float* c, const uint32_t* a, const uint32_t* b) {
    asm volatile(
        "mma.sync.aligned.m16n8k16.row.col.f32.bf16.bf16.f32 "
        "{%0,%1,%2,%3}, {%4,%5,%6,%7}, {%8,%9}, {%0,%1,%2,%3};\n"
        : "+f"(c[0]), "+f"(c[1]), "+f"(c[2]), "+f"(c[3])
        : "r"(a[0]), "r"(a[1]), "r"(a[2]), "r"(a[3]), "r"(b[0]), "r"(b[1]));
}

__device__ __forceinline__ void ldsm4(uint32_t& r0, uint32_t& r1, uint32_t& r2, uint32_t& r3, uint32_t a) {
    asm volatile("ldmatrix.sync.aligned.m8n8.x4.shared.b16 {%0,%1,%2,%3}, [%4];"
        : "=r"(r0), "=r"(r1), "=r"(r2), "=r"(r3) : "r"(a));
}

__device__ __forceinline__ void ldsm4t(uint32_t& r0, uint32_t& r1, uint32_t& r2, uint32_t& r3, uint32_t a) {
    asm volatile("ldmatrix.sync.aligned.m8n8.x4.trans.shared.b16 {%0,%1,%2,%3}, [%4];"
        : "=r"(r0), "=r"(r1), "=r"(r2), "=r"(r3) : "r"(a));
}

__device__ __forceinline__ uint32_t smem_u32(const void* p) {
    uint32_t a;
    asm("{ .reg .u64 t; cvta.to.shared.u64 t, %1; cvt.u32.u64 %0, t; }" : "=r"(a) : "l"(p));
    return a;
}

__device__ __forceinline__ void split2(float x0, float x1, uint32_t& hi, uint32_t& lo) {
    __nv_bfloat16 h0 = __float2bfloat16(x0), h1 = __float2bfloat16(x1);
    float r0 = x0 - __bfloat162float(h0), r1 = x1 - __bfloat162float(h1);
    __nv_bfloat16 l0 = __float2bfloat16(r0), l1 = __float2bfloat16(r1);
    hi = (uint32_t)__bfloat16_as_ushort(h0) | ((uint32_t)__bfloat16_as_ushort(h1) << 16);
    lo = (uint32_t)__bfloat16_as_ushort(l0) | ((uint32_t)__bfloat16_as_ushort(l1) << 16);
}

// ---------------- split kernels ----------------
__global__ void k_split(const float* __restrict__ src, uint32_t* __restrict__ dh,
                        uint32_t* __restrict__ dl, size_t npairs) {
    size_t i = (size_t)blockIdx.x * blockDim.x + threadIdx.x;
    if (i < npairs) {
        float2 v = ((const float2*)src)[i];
        uint32_t h, l; split2(v.x, v.y, h, l);
        dh[i] = h; dl[i] = l;
    }
}

__global__ void k_prep(const float* __restrict__ w2, const float* __restrict__ ew,
                       uint32_t* __restrict__ w2h, uint32_t* __restrict__ w2l,
                       uint32_t* __restrict__ ewth, uint32_t* __restrict__ ewtl) {
    int i = blockIdx.x * blockDim.x + threadIdx.x;
    if (i < NPAIR) {
        float2 v = ((const float2*)w2)[i];
        uint32_t h, l; split2(v.x, v.y, h, l);
        w2h[i] = h; w2l[i] = l;
        int lrow = i / 58, k2 = i - lrow*58;
        float a0 = ew[(2*k2)*R + lrow], a1 = ew[(2*k2+1)*R + lrow];
        split2(a0, a1, h, l);
        ewth[i] = h; ewtl[i] = l;
    }
}

// ======================= fused per-sample chain kernel (1024 thr) =======================
__device__ __forceinline__ void copyplane(uint32_t* dsth, uint32_t* dstl,
                                          const uint32_t* __restrict__ sh,
                                          const uint32_t* __restrict__ sl) {
    for (int e = threadIdx.x; e < NPAIR; e += CHT) {
        int r = e / 58, c = e - r*58;
        int o = r*CS32 + c;
        dsth[o] = sh[e]; dstl[o] = sl[e];
    }
}

// ldmatrix-based bf16x3 128x128x128 block mma (32 warps, warp tile 16x32)
__device__ __forceinline__ void tc4(uint32_t aAh, uint32_t aAl, uint32_t aBh, uint32_t aBl,
                                    int wr, int wc, int lane, float acc[4][4]) {
    int lrow = lane & 15, lh = lane >> 4;
    #pragma unroll
    for (int kk = 0; kk < 8; kk++) {
        uint32_t kbyt = (uint32_t)(kk * 8) * 4;
        uint32_t ah[4], al[4];
        {
            uint32_t off = (uint32_t)((wr + lrow)*CS32 + lh*4)*4 + kbyt;
            ldsm4(ah[0], ah[1], ah[2], ah[3], aAh + off);
            ldsm4(al[0], al[1], al[2], al[3], aAl + off);
        }
        #pragma unroll
        for (int jb = 0; jb < 2; jb++) {
            uint32_t off = (uint32_t)((wc + 16*jb + lrow)*CS32 + lh*4)*4 + kbyt;
            uint32_t h0,h1,h2,h3, l0,l1,l2,l3;
            ldsm4(h0, h1, h2, h3, aBh + off);
            ldsm4(l0, l1, l2, l3, aBl + off);
            uint32_t bh0[2] = {h0, h2}, bh1[2] = {h1, h3};
            uint32_t bl0[2] = {l0, l2}, bl1[2] = {l1, l3};
            int j0 = 2*jb, j1 = 2*jb + 1;
            mma16816(acc[j0], ah, bh0); mma16816(acc[j1], ah, bh1);
            mma16816(acc[j0], ah, bl0); mma16816(acc[j1], ah, bl1);
            mma16816(acc[j0], al, bh0); mma16816(acc[j1], al, bh1);
        }
    }
}

// variant: B read transposed directly from its natural [row][col] layout via ldmatrix.trans
// computes C = A @ B  (instead of A @ B^T): B fragment (k=src row j, n=src col)
__device__ __forceinline__ void tc4t(uint32_t aAh, uint32_t aAl, uint32_t aBh, uint32_t aBl,
                                     int wr, int wc, int lane, float acc[4][4]) {
    int lrow = lane & 15, lh = lane >> 4;
    #pragma unroll
    for (int kk = 0; kk < 8; kk++) {
        uint32_t kbyt = (uint32_t)(kk * 8) * 4;
        uint32_t ah[4], al[4];
        {
            uint32_t off = (uint32_t)((wr + lrow)*CS32 + lh*4)*4 + kbyt;
            ldsm4(ah[0], ah[1], ah[2], ah[3], aAh + off);
            ldsm4(al[0], al[1], al[2], al[3], aAl + off);
        }
        #pragma unroll
        for (int jb = 0; jb < 2; jb++) {
            // source rows j = kk*16 + lrow, cols (halves) = wc + 16*jb + lh*8
            uint32_t off = (uint32_t)((kk*16 + lrow)*CS32 + (wc + 16*jb)/2 + lh*4)*4;
            uint32_t t0,t1,t2,t3, s0,s1,s2,s3;
            ldsm4t(t0, t1, t2, t3, aBh + off);
            ldsm4t(s0, s1, s2, s3, aBl + off);
            uint32_t bh0[2] = {t0, t1}, bh1[2] = {t2, t3};
            uint32_t bl0[2] = {s0, s1}, bl1[2] = {s2, s3};
            int j0 = 2*jb, j1 = 2*jb + 1;
            mma16816(acc[j0], ah, bh0); mma16816(acc[j1], ah, bh1);
            mma16816(acc[j0], ah, bl0); mma16816(acc[j1], ah, bl1);
            mma16816(acc[j0], al, bh0); mma16816(acc[j1], al, bh1);
        }
    }
}

__device__ __forceinline__ void zacc(float acc[4][4]) {
    #pragma unroll
    for (int j = 0; j < 4; j++)
        #pragma unroll
        for (int q = 0; q < 4; q++) acc[j][q] = 0.f;
}

__device__ __forceinline__ void wtile(const float acc[4][4], uint32_t* Ph, uint32_t* Pl,
                                      const float* __restrict__ bv, int wr, int wc, int lane) {
    int lr = lane >> 2, lc = lane & 3;
    int r0 = wr + lr;
    #pragma unroll
    for (int j = 0; j < 4; j++) {
        int col = wc + 8*j + 2*lc;
        bool cok = col < R;
        float b0 = 0.f, b1v = 0.f;
        if (bv && cok) { b0 = bv[col]; b1v = bv[col+1]; }
        float v0 = (cok && r0   < R) ? acc[j][0] + b0  : 0.f;
        float v1 = (cok && r0   < R) ? acc[j][1] + b1v : 0.f;
        float v2 = (cok && r0+8 < R) ? acc[j][2] + b0  : 0.f;
        float v3 = (cok && r0+8 < R) ? acc[j][3] + b1v : 0.f;
        uint32_t h, l;
        split2(v0, v1, h, l); Ph[r0*CS32 + (col>>1)] = h; Pl[r0*CS32 + (col>>1)] = l;
        split2(v2, v3, h, l); Ph[(r0+8)*CS32 + (col>>1)] = h; Pl[(r0+8)*CS32 + (col>>1)] = l;
    }
}

__global__ void __launch_bounds__(CHT, 1)
k_chain(const uint32_t* __restrict__ Zh_g, const uint32_t* __restrict__ Zl_g,
        const float* __restrict__ Xg,
        const float* __restrict__ w1, const float* __restrict__ b1,
        const uint32_t* __restrict__ W2h, const uint32_t* __restrict__ W2l,
        const float* __restrict__ b2, const float* __restrict__ nw,
        const uint32_t* __restrict__ EwTh, const uint32_t* __restrict__ EwTl,
        float* __restrict__ Z2g, float* __restrict__ X1g) {
    extern __shared__ uint32_t sm[];
    uint32_t* sZh = sm;          uint32_t* sZl = sm + CPL;
    uint32_t* sBh = sm + 2*CPL;  uint32_t* sBl = sm + 3*CPL;
    uint32_t* sCh = sm + 4*CPL;  uint32_t* sCl = sm + 5*CPL;
    float* Sf = (float*)(sm + 4*CPL);
    __shared__ float sX[NF], sk[3*R], sA1[NF];

    int tid = threadIdx.x, lane = tid & 31, w = tid >> 5;
    int wr = (w & 7) * 16, wc = (w >> 3) * 32;
    size_t n = blockIdx.x;

    uint32_t uS = smem_u32(sm);
    uint32_t uZh = uS,            uZl = uS + CPL*4;
    uint32_t uBh = uS + 2*CPL*4,  uBl = uS + 3*CPL*4;
    uint32_t uCh = uS + 4*CPL*4,  uCl = uS + 5*CPL*4;

    for (int i = tid; i < 1464; i += CHT) {
        int r, wcd;
        if (i < 696) { r = i / 6; wcd = 58 + (i - r*6); }
        else { int j = i - 696; r = 116 + (j >> 6); wcd = j & 63; }
        int o = r*CS32 + wcd;
        sZh[o] = 0; sZl[o] = 0; sBh[o] = 0; sBl[o] = 0;
    }
    copyplane(sZh, sZl, Zh_g + n*NPAIR, Zl_g + n*NPAIR);
    copyplane(sBh, sBl, W2h, W2l);
    for (int e = tid; e < NF; e += CHT) sX[e] = Xg[n*(size_t)NF + e];
    __syncthreads();

    for (int e = tid; e < 3*R; e += CHT) {
        int c = e / R, l = e - c*R;
        sk[c*R + l] = b1[c] + w1[c*3]*sX[l*3] + w1[c*3+1]*sX[l*3+1] + w1[c*3+2]*sX[l*3+2];
    }
    __syncthreads();
    for (int e = tid; e < RR; e += CHT) {
        int l = e / R, m = e - l*R;
        Sf[l*117 + m] = sk[l]*sk[m] + sk[R+l]*sk[R+m] + sk[2*R+l]*sk[2*R+m];
    }
    __syncthreads();

    // mma1: ZW = Z @ W2^T
    float acc[4][4];
    zacc(acc);
    tc4(uZh, uZl, uBh, uBl, wr, wc, lane, acc);
    __syncthreads();

    // softmax(S) -> att into sB
    for (int l = w; l < R; l += 32) {
        const float* Srow = Sf + l*117;
        bool sec = lane < 26;
        float a0 = Srow[2*lane], a1 = Srow[2*lane+1];
        float a2 = sec ? Srow[64+2*lane] : -1e30f;
        float a3 = sec ? Srow[65+2*lane] : -1e30f;
        float mx = fmaxf(fmaxf(a0, a1), fmaxf(a2, a3));
        #pragma unroll
        for (int o = 16; o; o >>= 1) mx = fmaxf(mx, __shfl_xor_sync(0xffffffffu, mx, o));
        float e0 = expf(a0-mx), e1 = expf(a1-mx);
        float e2 = sec ? expf(a2-mx) : 0.f, e3 = sec ? expf(a3-mx) : 0.f;
        float sum = e0+e1+e2+e3;
        #pragma unroll
        for (int o = 16; o; o >>= 1) sum += __shfl_xor_sync(0xffffffffu, sum, o);
        float inv = 1.f / sum;
        uint32_t h, lo;
        split2(e0*inv, e1*inv, h, lo);
        sBh[l*CS32 + lane] = h; sBl[l*CS32 + lane] = lo;
        if (sec) {
            split2(e2*inv, e3*inv, h, lo);
            sBh[l*CS32 + 32+lane] = h; sBl[l*CS32 + 32+lane] = lo;
        }
    }
    __syncthreads();

    // ZW (+conv2_b) -> sC
    wtile(acc, sCh, sCl, b2, wr, wc, lane);
    __syncthreads();

    // mma2: P = ZW @ att^T
    zacc(acc);
    tc4(uCh, uCl, uBh, uBl, wr, wc, lane, acc);
    __syncthreads();

    // P -> sC (Z stays in sZ; mma3 reads it transposed via ldmatrix.trans)
    wtile(acc, sCh, sCl, (const float*)0, wr, wc, lane);
    __syncthreads();

    // mma3: T = P @ Z  (B = Z read transposed in-place)
    float accT[4][4];
    zacc(accT);
    tc4t(uCh, uCl, uZh, uZl, wr, wc, lane, accT);

    // X1 stage1: A1 = P @ X (P in sC)
    if (tid < NF) {
        int m = tid / 3, f = tid - m*3;
        float a = 0.f;
        for (int p = 0; p < 58; p++) {
            uint32_t hw = sCh[m*CS32 + p], lw = sCl[m*CS32 + p];
            __nv_bfloat162 hb = *reinterpret_cast<__nv_bfloat162*>(&hw);
            __nv_bfloat162 lb = *reinterpret_cast<__nv_bfloat162*>(&lw);
            float p0 = __low2float(hb) + __low2float(lb);
            float p1 = __high2float(hb) + __high2float(lb);
            a += p0 * sX[(2*p)*3 + f] + p1 * sX[(2*p+1)*3 + f];
        }
        sA1[tid] = a;
    }
    __syncthreads();

    if (tid < NF) {
        int m = tid / 3, l = tid - m*3;
        X1g[n*(size_t)NF + tid] = sA1[m*3]*nw[l] + sA1[m*3+1]*nw[3+l] + sA1[m*3+2]*nw[6+l];
    }
    wtile(accT, sCh, sCl, (const float*)0, wr, wc, lane);
    copyplane(sBh, sBl, EwTh, EwTl);
    __syncthreads();

    // mma4: Z2 = T @ EwT^T
    zacc(acc);
    tc4(uCh, uCl, uBh, uBl, wr, wc, lane, acc);

    float* out = Z2g + n*(size_t)RR;
    int lr = lane >> 2, lc = lane & 3;
    int r0 = wr + lr;
    #pragma unroll
    for (int j = 0; j < 4; j++) {
        int col = wc + 8*j + 2*lc;
        if (col >= R) continue;
        if (r0 < R) {
            out[r0*R + col]   = acc[j][0];
            out[r0*R + col+1] = acc[j][1];
        }
        if (r0 + 8 < R) {
            out[(r0+8)*R + col]   = acc[j][2];
            out[(r0+8)*R + col+1] = acc[j][3];
        }
    }
}

// ---------------- pre-split big GEMM (headZ, split-K, K-stage=32): C_partial = A @ B^T ----------------
__global__ void __launch_bounds__(256)
k_tc_pre(const uint32_t* __restrict__ Ah_g, const uint32_t* __restrict__ Al_g,
         const uint32_t* __restrict__ Bh_g, const uint32_t* __restrict__ Bl_g,
         float* __restrict__ C, int M, int N, int K2, int kChunk2) {
    extern __shared__ uint32_t sm[];
    int tid = threadIdx.x, lane = tid & 31, w = tid >> 5;
    int warpRow = (w & 3) * 32, warpCol = (w >> 2) * 64;
    int bm = blockIdx.y * 128, bn = blockIdx.x * 128;
    int kb = blockIdx.z * kChunk2;
    int ke = min(kb + kChunk2, K2);
    int nst = (ke - kb + 15) / 16;

    float acc[2][8][4];
    #pragma unroll
    for (int mi = 0; mi < 2; mi++)
        #pragma unroll
        for (int j = 0; j < 8; j++)
            #pragma unroll
            for (int q = 0; q < 4; q++) acc[mi][j][q] = 0.f;

    int r0t = tid >> 2;
    int c4 = (tid & 3) * 4;

    uint4 vah[2], val_[2], vbh[2], vbl[2];
    auto ldt = [&](int s) {
        int ku = kb + s*16 + c4;
        bool ok = (ku + 4) <= ke;
        const uint4 z4 = make_uint4(0,0,0,0);
        #pragma unroll
        for (int q = 0; q < 2; q++) {
            int r = r0t + 64*q;
            size_t ao = (size_t)(bm + r) * K2 + ku;
            size_t bo = (size_t)(bn + r) * K2 + ku;
            vah[q] = ok ? *(const uint4*)(Ah_g + ao) : z4;
            val_[q] = ok ? *(const uint4*)(Al_g + ao) : z4;
            vbh[q] = ok ? *(const uint4*)(Bh_g + bo) : z4;
            vbl[q] = ok ? *(const uint4*)(Bl_g + bo) : z4;
        }
    };
    auto stt = [&](int buf) {
        uint32_t* Ah = sm + buf*4*BPL;
        uint32_t* Al = Ah + BPL;
        uint32_t* Bh = Ah + 2*BPL;
        uint32_t* Bl = Ah + 3*BPL;
        #pragma unroll
        for (int q = 0; q < 2; q++) {
            int r = r0t + 64*q;
            *(uint4*)(Ah + r*BS32 + c4) = vah[q];
            *(uint4*)(Al + r*BS32 + c4) = val_[q];
            *(uint4*)(Bh + r*BS32 + c4) = vbh[q];
            *(uint4*)(Bl + r*BS32 + c4) = vbl[q];
        }
    };

    ldt(0); stt(0);
    __syncthreads();
    for (int s = 0; s < nst; s++) {
        if (s + 1 < nst) ldt(s + 1);
        const uint32_t* base = sm + (s & 1) * 4 * BPL;
        {
            const uint32_t* Ah = base; const uint32_t* Al = base + BPL;
            const uint32_t* Bh = base + 2*BPL; const uint32_t* Bl = base + 3*BPL;
            int lr = lane >> 2, lc = lane & 3;
            for (int kk = 0; kk < 2; kk++) {
                int kp = kk*8 + lc;
                uint32_t ah[2][4], al[2][4];
                #pragma unroll
                for (int mi = 0; mi < 2; mi++) {
                    int r = warpRow + 16*mi + lr;
                    ah[mi][0] = Ah[r*BS32+kp];     ah[mi][1] = Ah[(r+8)*BS32+kp];
                    ah[mi][2] = Ah[r*BS32+kp+4];   ah[mi][3] = Ah[(r+8)*BS32+kp+4];
                    al[mi][0] = Al[r*BS32+kp];     al[mi][1] = Al[(r+8)*BS32+kp];
                    al[mi][2] = Al[r*BS32+kp+4];   al[mi][3] = Al[(r+8)*BS32+kp+4];
                }
                #pragma unroll
                for (int j = 0; j < 8; j++) {
                    int nr = warpCol + 8*j + lr;
                    uint32_t bh[2] = {Bh[nr*BS32+kp], Bh[nr*BS32+kp+4]};
                    uint32_t bl[2] = {Bl[nr*BS32+kp], Bl[nr*BS32+kp+4]};
                    mma16816(acc[0][j], ah[0], bh);
                    mma16816(acc[1][j], ah[1], bh);
                    mma16816(acc[0][j], ah[0], bl);
                    mma16816(acc[1][j], ah[1], bl);
                    mma16816(acc[0][j], al[0], bh);
                    mma16816(acc[1][j], al[1], bh);
                }
            }
        }
        if (s + 1 < nst) stt((s + 1) & 1);
        __syncthreads();
    }

    int lr = lane >> 2, lc = lane & 3;
    float* Cp = C + (size_t)blockIdx.z * M * N;
    #pragma unroll
    for (int mi = 0; mi < 2; mi++) {
        int row0 = bm + warpRow + 16*mi + lr;
        #pragma unroll
        for (int j = 0; j < 8; j++) {
            int col = bn + warpCol + 8*j + 2*lc;
            if (col >= N) continue;
            Cp[(size_t)row0*N + col]     = acc[mi][j][0];
            Cp[(size_t)row0*N + col + 1] = acc[mi][j][1];
            Cp[(size_t)(row0+8)*N + col]     = acc[mi][j][2];
            Cp[(size_t)(row0+8)*N + col + 1] = acc[mi][j][3];
        }
    }
}

// ---------------- fp32-input big GEMM (c1): C = relu(A @ B^T + bias) ----------------
__global__ void __launch_bounds__(256)
k_tc_big(const float* __restrict__ A, const float* __restrict__ B,
         const float* __restrict__ bias, float* __restrict__ C,
         int M, int N, int K) {
    extern __shared__ uint32_t sm[];
    int tid = threadIdx.x, lane = tid & 31, w = tid >> 5;
    int warpRow = (w & 3) * 32, warpCol = (w >> 2) * 64;
    int bm = blockIdx.y * 128, bn = blockIdx.x * 128;
    int nst = (K + 31) / 32;

    float acc[2][8][4];
    #pragma unroll
    for (int mi = 0; mi < 2; mi++)
        #pragma unroll
        for (int j = 0; j < 8; j++)
            #pragma unroll
            for (int q = 0; q < 4; q++) acc[mi][j][q] = 0.f;

    int rA = tid >> 3;
    int cG = (tid & 7) * 4;

    auto ldtile = [&](int s, float4* va, float4* vb) {
        int k0 = s*32 + cG;
        bool kok = (k0 + 4 <= K);
        #pragma unroll
        for (int q = 0; q < 4; q++) {
            const float* ap = A + (size_t)(bm + rA + 32*q) * K;
            va[q] = kok ? *(const float4*)(ap + k0) : make_float4(0.f,0.f,0.f,0.f);
            int br = bn + rA + 32*q;
            const float* bp = B + (size_t)br * K;
            vb[q] = (kok && br < N) ? *(const float4*)(bp + k0) : make_float4(0.f,0.f,0.f,0.f);
        }
    };
    auto sttile = [&](int buf, const float4* va, const float4* vb) {
        uint32_t* Ah = sm + buf*4*BPL;
        uint32_t* Al = Ah + BPL;
        uint32_t* Bh = Ah + 2*BPL;
        uint32_t* Bl = Ah + 3*BPL;
        int kp = cG >> 1;
        #pragma unroll
        for (int q = 0; q < 4; q++) {
            int r = rA + 32*q;
            uint32_t h, l;
            split2(va[q].x, va[q].y, h, l); Ah[r*BS32+kp]   = h; Al[r*BS32+kp]   = l;
            split2(va[q].z, va[q].w, h, l); Ah[r*BS32+kp+1] = h; Al[r*BS32+kp+1] = l;
            split2(vb[q].x, vb[q].y, h, l); Bh[r*BS32+kp]   = h; Bl[r*BS32+kp]   = l;
            split2(vb[q].z, vb[q].w, h, l); Bh[r*BS32+kp+1] = h; Bl[r*BS32+kp+1] = l;
        }
    };

    {
        float4 va[4], vb[4];
        ldtile(0, va, vb);
        sttile(0, va, vb);
    }
    __syncthreads();
    for (int s = 0; s < nst; s++) {
        float4 va[4], vb[4];
        if (s + 1 < nst) ldtile(s + 1, va, vb);
        const uint32_t* base = sm + (s & 1) * 4 * BPL;
        {
            const uint32_t* Ah = base; const uint32_t* Al = base + BPL;
            const uint32_t* Bh = base + 2*BPL; const uint32_t* Bl = base + 3*BPL;
            int lr = lane >> 2, lc = lane & 3;
            for (int kk = 0; kk < 2; kk++) {
                int kp = kk*8 + lc;
                uint32_t ah[2][4], al[2][4];
                #pragma unroll
                for (int mi = 0; mi < 2; mi++) {
                    int r = warpRow + 16*mi + lr;
                    ah[mi][0] = Ah[r*BS32+kp];     ah[mi][1] = Ah[(r+8)*BS32+kp];
                    ah[mi][2] = Ah[r*BS32+kp+4];   ah[mi][3] = Ah[(r+8)*BS32+kp+4];
                    al[mi][0] = Al[r*BS32+kp];     al[mi][1] = Al[(r+8)*BS32+kp];
                    al[mi][2] = Al[r*BS32+kp+4];   al[mi][3] = Al[(r+8)*BS32+kp+4];
                }
                #pragma unroll
                for (int j = 0; j < 8; j++) {
                    int nr = warpCol + 8*j + lr;
                    uint32_t bh[2] = {Bh[nr*BS32+kp], Bh[nr*BS32+kp+4]};
                    uint32_t bl[2] = {Bl[nr*BS32+kp], Bl[nr*BS32+kp+4]};
                    mma16816(acc[0][j], ah[0], bh);
                    mma16816(acc[1][j], ah[1], bh);
                    mma16816(acc[0][j], ah[0], bl);
                    mma16816(acc[1][j], ah[1], bl);
                    mma16816(acc[0][j], al[0], bh);
                    mma16816(acc[1][j], al[1], bh);
                }
            }
        }
        if (s + 1 < nst) sttile((s + 1) & 1, va, vb);
        __syncthreads();
    }

    int lr = lane >> 2, lc = lane & 3;
    #pragma unroll
    for (int mi = 0; mi < 2; mi++) {
        int row0 = bm + warpRow + 16*mi + lr;
        #pragma unroll
        for (int j = 0; j < 8; j++) {
            int col = bn + warpCol + 8*j + 2*lc;
            if (col >= N) continue;
            float b0 = bias[col], b1 = bias[col+1];
            float v0 = fmaxf(acc[mi][j][0] + b0, 0.f), v1 = fmaxf(acc[mi][j][1] + b1, 0.f);
            float v2 = fmaxf(acc[mi][j][2] + b0, 0.f), v3 = fmaxf(acc[mi][j][3] + b1, 0.f);
            C[(size_t)row0*N + col]     = v0;
            C[(size_t)row0*N + col + 1] = v1;
            C[(size_t)(row0+8)*N + col]     = v2;
            C[(size_t)(row0+8)*N + col + 1] = v3;
        }
    }
}

// ---------------- misc kernels ----------------
__global__ void k_copy(float* __restrict__ dst, const float* __restrict__ src, size_t n) {
    size_t i = (size_t)blockIdx.x * blockDim.x + threadIdx.x;
    if (i < n) dst[i] = src[i];
}

// two-phase channel stats for LD=R (Z2)
__global__ void k_chanpart(const float* __restrict__ src, double* __restrict__ ps) {
    int ch = blockIdx.x, slab = blockIdx.y, tid = threadIdx.x;
    int nPer = NB / SLABS;
    int n0 = slab * nPer;
    double s = 0.0, q = 0.0;
    for (int e = tid; e < nPer * R; e += 256) {
        int n = n0 + e / R, l = e - (e / R) * R;
        double v = (double)src[(size_t)n*RR + (size_t)ch*R + l];
        s += v; q += v*v;
    }
    __shared__ double shs[256], shq[256];
    shs[tid] = s; shq[tid] = q;
    __syncthreads();
    for (int o = 128; o > 0; o >>= 1) {
        if (tid < o) { shs[tid] += shs[tid+o]; shq[tid] += shq[tid+o]; }
        __syncthreads();
    }
    if (tid == 0) {
        ps[(ch*SLABS + slab)*2]     = shs[0];
        ps[(ch*SLABS + slab)*2 + 1] = shq[0];
    }
}

__global__ void k_chanfin(const double* __restrict__ ps,
                          float* __restrict__ mean, float* __restrict__ rstd) {
    int ch = threadIdx.x;
    if (ch < R) {
        double s = 0.0, q = 0.0;
        #pragma unroll
        for (int k = 0; k < SLABS; k++) {
            s += ps[(ch*SLABS + k)*2];
            q += ps[(ch*SLABS + k)*2 + 1];
        }
        double tot = (double)NB * R;
        double m = s / tot;
        double var = q / tot - m*m;
        mean[ch] = (float)m;
        rstd[ch] = rsqrtf((float)var + EPSBN);
    }
}

__global__ void k_chanstats(const float* __restrict__ src, int LD,
                            float* __restrict__ mean, float* __restrict__ rstd) {
    int i = blockIdx.x, tid = threadIdx.x;
    int tot = NB * LD;
    double s = 0.0, q = 0.0;
    for (int e = tid; e < tot; e += blockDim.x) {
        int n = e / LD, l = e % LD;
        double v = (double)src[(size_t)n*(R*LD) + (size_t)i*LD + l];
        s += v; q += v*v;
    }
    __shared__ double shs[256], shq[256];
    shs[tid] = s; shq[tid] = q;
    __syncthreads();
    for (int o = blockDim.x >> 1; o > 0; o >>= 1) {
        if (tid < o) { shs[tid] += shs[tid+o]; shq[tid] += shq[tid+o]; }
        __syncthreads();
    }
    if (tid == 0) {
        double m = shs[0] / tot;
        double var = shq[0] / tot - m*m;
        mean[i] = (float)m;
        rstd[i] = rsqrtf((float)var + EPSBN);
    }
}

// BN+residual for Z operating directly on bf16 hi/lo planes
__global__ void k_updateZ(uint32_t* __restrict__ zh, uint32_t* __restrict__ zl,
                          const float* __restrict__ src,
                          const float* __restrict__ mean, const float* __restrict__ rstd,
                          const float* __restrict__ gg, const float* __restrict__ bb) {
    size_t idx2 = (size_t)blockIdx.x * blockDim.x + threadIdx.x;
    if (idx2 >= (size_t)NB*NPAIR) return;
    int p = (int)(idx2 % NPAIR);
    int i = p / 58;
    float2 s2 = ((const float2*)src)[idx2];
    uint32_t h = zh[idx2], l = zl[idx2];
    __nv_bfloat162 hb = *reinterpret_cast<__nv_bfloat162*>(&h);
    __nv_bfloat162 lb = *reinterpret_cast<__nv_bfloat162*>(&l);
    float z0 = __low2float(hb) + __low2float(lb);
    float z1 = __high2float(hb) + __high2float(lb);
    float m = mean[i], rs = rstd[i], ga = gg[i], be = bb[i];
    z0 += fmaxf((s2.x - m)*rs*ga + be, 0.f);
    z1 += fmaxf((s2.y - m)*rs*ga + be, 0.f);
    split2(z0, z1, h, l);
    zh[idx2] = h; zl[idx2] = l;
}

__global__ void k_update(float* __restrict__ buf, const float* __restrict__ src, int LD,
                         const float* __restrict__ mean, const float* __restrict__ rstd,
                         const float* __restrict__ g, const float* __restrict__ b) {
    size_t idx = (size_t)blockIdx.x * blockDim.x + threadIdx.x;
    size_t tot = (size_t)NB * R * LD;
    if (idx < tot) {
        int i = (int)((idx / LD) % R);
        float v = (src[idx] - mean[i]) * rstd[i] * g[i] + b[i];
        buf[idx] += fmaxf(v, 0.f);
    }
}

__global__ void __launch_bounds__(256)
k_gemm(const float* __restrict__ A, const float* __restrict__ W,
       const float* __restrict__ bias, float* __restrict__ Cm,
       int M, int Nc, int K) {
    __shared__ float sA[16][68];
    __shared__ float sB[16][68];
    int tid = threadIdx.x;
    int tx = tid & 15, ty = tid >> 4;
    int bm = blockIdx.y * 64, bn = blockIdx.x * 64;
    float acc[4][4];
    #pragma unroll
    for (int i = 0; i < 4; i++)
        #pragma unroll
        for (int j = 0; j < 4; j++) acc[i][j] = 0.f;

    for (int k0 = 0; k0 < K; k0 += 16) {
        #pragma unroll
        for (int q = 0; q < 4; q++) {
            int e = tid + 256*q;
            int r = e >> 4, c = e & 15;
            int gc = k0 + c;
            float av = 0.f, wv = 0.f;
            if (gc < K) {
                av = A[(size_t)(bm + r) * K + gc];
                wv = W[(size_t)(bn + r) * K + gc];
            }
            sA[c][r] = av;
            sB[c][r] = wv;
        }
        __syncthreads();
        #pragma unroll
        for (int kk = 0; kk < 16; kk++) {
            float4 a4 = *(const float4*)&sA[kk][ty*4];
            float4 b4 = *(const float4*)&sB[kk][tx*4];
            float a[4] = {a4.x, a4.y, a4.z, a4.w};
            float b[4] = {b4.x, b4.y, b4.z, b4.w};
            #pragma unroll
            for (int i = 0; i < 4; i++)
                #pragma unroll
                for (int j = 0; j < 4; j++) acc[i][j] += a[i]*b[j];
        }
        __syncthreads();
    }
    #pragma unroll
    for (int i = 0; i < 4; i++) {
        int row = bm + ty*4 + i;
        #pragma unroll
        for (int j = 0; j < 4; j++) {
            int col = bn + tx*4 + j;
            float v = acc[i][j] + bias[col];
            v = fmaxf(v, 0.f);
            Cm[(size_t)row * Nc + col] = v;
        }
    }
}

__global__ void k_colstats(const float* __restrict__ Y, int C,
                           float* __restrict__ mean, float* __restrict__ rstd) {
    int c = blockIdx.x, tid = threadIdx.x;
    double s = 0.0, q = 0.0;
    for (int r = tid; r < NB; r += blockDim.x) {
        double v = (double)Y[(size_t)r*C + c];
        s += v; q += v*v;
    }
    __shared__ double shs[256], shq[256];
    shs[tid] = s; shq[tid] = q;
    __syncthreads();
    for (int o = blockDim.x >> 1; o > 0; o >>= 1) {
        if (tid < o) { shs[tid] += shs[tid+o]; shq[tid] += shq[tid+o]; }
        __syncthreads();
    }
    if (tid == 0) {
        double m = shs[0] / NB;
        double var = shq[0] / NB - m*m;
        mean[c] = (float)m;
        rstd[c] = rsqrtf((float)var + EPSBN);
    }
}

__global__ void k_bnapply(const float* __restrict__ Y, int C, int off,
                          const float* __restrict__ mean, const float* __restrict__ rstd,
                          const float* __restrict__ g, const float* __restrict__ b,
                          float* __restrict__ XZ) {
    int idx = blockIdx.x * blockDim.x + threadIdx.x;
    if (idx < NB * C) {
        int r = idx / C, c = idx % C;
        XZ[(size_t)r*CC + off + c] = (Y[idx] - mean[c]) * rstd[c] * g[c] + b[c];
    }
}

__global__ void k_redz(const float* __restrict__ parts, const float* __restrict__ bias,
                       float* __restrict__ out) {
    int idx = blockIdx.x * blockDim.x + threadIdx.x;
    if (idx < NB * H3) {
        int c = idx % H3;
        float s = bias[c];
        #pragma unroll
        for (int k = 0; k < SPLITS; k++) s += parts[(size_t)k*NB*H3 + idx];
        out[idx] = fmaxf(s, 0.f);
    }
}

__global__ void k_c2(const float* __restrict__ hbuf, const float* __restrict__ w,
                     const float* __restrict__ b, float* __restrict__ out) {
    int gw = (blockIdx.x * blockDim.x + threadIdx.x) >> 5;
    int lane = threadIdx.x & 31;
    if (gw >= NB) return;
    const float* hrow = hbuf + (size_t)gw * C1;
    float s0 = 0.f, s1 = 0.f;
    for (int k = lane; k < C1; k += 32) {
        float hv = hrow[k];
        s0 += hv * w[k];
        s1 += hv * w[C1 + k];
    }
    #pragma unroll
    for (int o = 16; o; o >>= 1) {
        s0 += __shfl_xor_sync(0xffffffffu, s0, o);
        s1 += __shfl_xor_sync(0xffffffffu, s1, o);
    }
    if (lane == 0) { out[gw*2 + 0] = s0 + b[0]; out[gw*2 + 1] = s1 + b[1]; }
}

// ---------------- host ----------------
extern "C" void kernel_launch(void* const* d_in, const int* in_sizes, int n_in,
                              void* d_out, int out_size) {
    const float* Xin     = (const float*)d_in[0];
    const float* Zin     = (const float*)d_in[1];
    const float* conv1_w = (const float*)d_in[2];
    const float* conv1_b = (const float*)d_in[3];
    const float* conv2_w = (const float*)d_in[4];
    const float* conv2_b = (const float*)d_in[5];
    const float* node_w  = (const float*)d_in[6];
    const float* edge_w  = (const float*)d_in[7];
    const float* bn_n_g  = (const float*)d_in[8];
    const float* bn_n_b  = (const float*)d_in[9];
    const float* bn_e_g  = (const float*)d_in[10];
    const float* bn_e_b  = (const float*)d_in[11];
    const float* ln_w    = (const float*)d_in[12];
    const float* ln_b    = (const float*)d_in[13];
    const float* ln_bn_g = (const float*)d_in[14];
    const float* ln_bn_b = (const float*)d_in[15];
    const float* le_w    = (const float*)d_in[16];
    const float* le_b    = (const float*)d_in[17];
    const float* le_bn_g = (const float*)d_in[18];
    const float* le_bn_b = (const float*)d_in[19];
    const float* c1_w    = (const float*)d_in[20];
    const float* c1_b    = (const float*)d_in[21];
    const float* c2_w    = (const float*)d_in[22];
    const float* c2_b    = (const float*)d_in[23];
    float* outp = (float*)d_out;

    float *pX, *pZ2, *pX1, *pYx, *pYz, *pYzS, *pXZ, *pH;
    float *pM1, *pR1, *pMz, *pRz, *pMx, *pRx;
    double* pPS;
    uint32_t *pZh, *pZl, *pLWh, *pLWl, *pW2h, *pW2l, *pEwTh, *pEwTl;
    cudaGetSymbolAddress((void**)&pX,   g_X);
    cudaGetSymbolAddress((void**)&pZ2,  g_Z2);
    cudaGetSymbolAddress((void**)&pX1,  g_X1);
    cudaGetSymbolAddress((void**)&pYx,  g_Yx);
    cudaGetSymbolAddress((void**)&pYz,  g_Yz);
    cudaGetSymbolAddress((void**)&pYzS, g_YzS);
    cudaGetSymbolAddress((void**)&pXZ,  g_XZ);
    cudaGetSymbolAddress((void**)&pH,   g_Hb);
    cudaGetSymbolAddress((void**)&pZh,  g_Zh);
    cudaGetSymbolAddress((void**)&pZl,  g_Zl);
    cudaGetSymbolAddress((void**)&pLWh, g_LWh);
    cudaGetSymbolAddress((void**)&pLWl, g_LWl);
    cudaGetSymbolAddress((void**)&pW2h, g_W2h);
    cudaGetSymbolAddress((void**)&pW2l, g_W2l);
    cudaGetSymbolAddress((void**)&pEwTh, g_EwTh);
    cudaGetSymbolAddress((void**)&pEwTl, g_EwTl);
    cudaGetSymbolAddress((void**)&pPS,  g_ps);
    cudaGetSymbolAddress((void**)&pM1,  g_m1);
    cudaGetSymbolAddress((void**)&pR1,  g_r1);
    cudaGetSymbolAddress((void**)&pMz,  g_mz);
    cudaGetSymbolAddress((void**)&pRz,  g_rz);
    cudaGetSymbolAddress((void**)&pMx,  g_mx);
    cudaGetSymbolAddress((void**)&pRx,  g_rx);

    cudaFuncSetAttribute(k_chain, cudaFuncAttributeMaxDynamicSharedMemorySize, CH_SMEM);
    cudaFuncSetAttribute(k_tc_pre, cudaFuncAttributeMaxDynamicSharedMemorySize, BIG_SMEM);
    cudaFuncSetAttribute(k_tc_big, cudaFuncAttributeMaxDynamicSharedMemorySize, BIG_SMEM);

    auto chain = [&](int i) {
        k_prep<<<(NPAIR + 255)/256, 256>>>(conv2_w + (size_t)i*RR, edge_w + (size_t)i*RR,
                                           pW2h, pW2l, pEwTh, pEwTl);
        k_chain<<<NB, CHT, CH_SMEM>>>(pZh, pZl, pX,
                                      conv1_w + i*9, conv1_b + i*3,
                                      pW2h, pW2l, conv2_b + i*R,
                                      node_w + i*9, pEwTh, pEwTl, pZ2, pX1);
    };
    auto headZgemm = [&](int i) {
        k_tc_pre<<<dim3(H3/128, NB/128, SPLITS), 256, BIG_SMEM>>>(
            pZh, pZl, pLWh + (size_t)i*H3*NPAIR, pLWl + (size_t)i*H3*NPAIR,
            pYzS, NB, H3, NPAIR, KCHUNK2);
    };
    auto headZpost = [&](int i) {
        k_redz<<<(NB*H3 + 255)/256, 256>>>(pYzS, le_b + i*H3, pYz);
        k_colstats<<<H3, 256>>>(pYz, H3, pM1, pR1);
        k_bnapply<<<(NB*H3 + 255)/256, 256>>>(pYz, H3, 5*H + i*H3, pM1, pR1, le_bn_g + i*H3, le_bn_b + i*H3, pXZ);
    };
    auto headX = [&](int i) {
        k_gemm<<<dim3(H/64, NB/64), 256>>>(pX, ln_w + (size_t)i*H*NF, ln_b + i*H, pYx, NB, H, NF);
        k_colstats<<<H, 256>>>(pYx, H, pM1, pR1);
        k_bnapply<<<(NB*H + 255)/256, 256>>>(pYx, H, i*H, pM1, pR1, ln_bn_g + i*H, ln_bn_b + i*H, pXZ);
    };

    // startup ordered so launch index 3 (0-based) = k_chain (ncu capture slot)
    k_copy<<<(NB*NF + 255)/256, 256>>>(pX, Xin, (size_t)NB*NF);                                    // 0
    k_split<<<(int)(((size_t)NB*NPAIR + 255)/256), 256>>>(Zin, pZh, pZl, (size_t)NB*NPAIR);        // 1
    chain(0);                                                                                      // 2: k_prep, 3: k_chain <- profiled
    k_split<<<(int)(((size_t)5*H3*NPAIR + 255)/256), 256>>>(le_w, pLWh, pLWl, (size_t)5*H3*NPAIR);
    headZgemm(0);
    headZpost(0);
    headX(0);

    for (int i = 0; i < 4; i++) {
        if (i > 0) chain(i);
        // edge BN stats (two-phase), residual on planes, then Z head
        k_chanpart<<<dim3(R, SLABS), 256>>>(pZ2, pPS);
        k_chanfin<<<1, 128>>>(pPS, pMz, pRz);
        k_updateZ<<<(int)(((size_t)NB*NPAIR + 255)/256), 256>>>(pZh, pZl, pZ2, pMz, pRz,
                                                                bn_e_g + i*R, bn_e_b + i*R);
        headZgemm(i + 1);
        headZpost(i + 1);
        // node BN + residual, then X head
        k_chanstats<<<R, 256>>>(pX1, 3, pMx, pRx);
        k_update<<<(NB*NF + 255)/256, 256>>>(pX, pX1, 3, pMx, pRx, bn_n_g + i*R, bn_n_b + i*R);
        headX(i + 1);
    }

    k_tc_big<<<dim3(C1/128, NB/128, 1), 256, BIG_SMEM>>>(pXZ, c1_w, c1_b, pH, NB, C1, CC);
    k_c2<<<NB*32/256, 256>>>(pH, c2_w, c2_b, outp);
}